// round 1
// baseline (speedup 1.0000x reference)
#include <cuda_runtime.h>
#include <math.h>

// Problem constants
// B=16, N=196, KV=960, H=4, chs = {64,128,256,512}

#define BM 64
#define BN 64
#define BK 16

#define MODE_K   0
#define MODE_V   1
#define MODE_Q   2
#define MODE_S   3
#define MODE_CTX 4
#define MODE_OUT 5

// Scratch (device globals: allocation-free, harness-legal)
__device__ float g_Kt [(size_t)4 * 16 * 960 * 196];   // [h][b][j][n]
__device__ float g_V  [(size_t)16 * 196 * 3840];      // [b][n][h*960+j]
__device__ float g_Q  [(size_t)64 * 512 * 196];       // [(b*4+h)][d][n]  (max ch)
__device__ float g_S  [(size_t)16 * 512 * 3840];      // [b][d][h*960+j]  (max ch)
__device__ float g_ctx[(size_t)16 * 196 * 512];       // [b][n][d]
__device__ float g_stats[128];                        // per (b*4+h): sum, sumsq

// ---------------------------------------------------------------------------
// Generic NT GEMM: C[m][n] = alpha * sum_k A[m][k] * B[n][k]
// k is contiguous in both operands for every mode (layouts chosen for this).
// 64x64 tile, 256 threads, 4x4 register microtile, BK=16.
// ---------------------------------------------------------------------------
template <int MODE>
__global__ __launch_bounds__(256)
void gemm_nt(const float* __restrict__ Ag, const float* __restrict__ Bg,
             float* __restrict__ Cg,
             int M, int N, int K, int lda, int ldb, int ch, float alpha)
{
    __shared__ float As[BK][BM];
    __shared__ float Bs[BK][BN];

    const int z = blockIdx.z;

    const float* A;
    const float* B;
    if (MODE == MODE_K || MODE == MODE_V) {
        A = Ag;                                   // emb_all  [3136][960]
        B = Bg + (size_t)z * 960 * 960;           // Wk/Wv head z
    } else if (MODE == MODE_Q) {
        int b = z >> 2, h = z & 3;
        A = Ag + (size_t)h * ch * ch;             // Wq[h]    [ch][ch]
        B = Bg + (size_t)b * 196 * ch;            // emb[b]   [196][ch]
    } else if (MODE == MODE_S) {
        int b = z >> 2, h = z & 3;
        A = g_Q  + (size_t)z * ch * 196;          // Q[b,h]   [ch][196]
        B = g_Kt + (size_t)(h * 16 + b) * 960 * 196; // Kt[h,b] [960][196]
    } else if (MODE == MODE_CTX) {
        A = g_V + (size_t)z * 196 * 3840;         // V[b]     [196][3840]
        B = g_S + (size_t)z * ch * 3840;          // probs[b] [ch][3840]
    } else { // MODE_OUT
        A = g_ctx + (size_t)z * 196 * ch;         // ctx[b]   [196][ch]
        B = Bg;                                   // Wo       [ch][ch]
    }

    const int tid  = threadIdx.x;
    const int tx   = tid & 15;
    const int ty   = tid >> 4;
    const int rowL = tid >> 2;          // 0..63 (tile row for loads)
    const int kq   = (tid & 3) * 4;     // 0,4,8,12

    const int m0 = blockIdx.y * BM;
    const int n0 = blockIdx.x * BN;

    float acc[4][4];
#pragma unroll
    for (int i = 0; i < 4; i++)
#pragma unroll
        for (int j = 0; j < 4; j++) acc[i][j] = 0.0f;

    for (int k0 = 0; k0 < K; k0 += BK) {
        // Load A tile (64 rows x 16 k), transposed into As[k][m]
        {
            int gm = m0 + rowL;
            float4 v = make_float4(0.f, 0.f, 0.f, 0.f);
            if (gm < M && (k0 + kq) < K)
                v = *(const float4*)(A + (size_t)gm * lda + k0 + kq);
            As[kq + 0][rowL] = v.x;
            As[kq + 1][rowL] = v.y;
            As[kq + 2][rowL] = v.z;
            As[kq + 3][rowL] = v.w;
        }
        // Load B tile (64 cols x 16 k), transposed into Bs[k][n]
        {
            int gn = n0 + rowL;
            float4 v = make_float4(0.f, 0.f, 0.f, 0.f);
            if (gn < N && (k0 + kq) < K)
                v = *(const float4*)(B + (size_t)gn * ldb + k0 + kq);
            Bs[kq + 0][rowL] = v.x;
            Bs[kq + 1][rowL] = v.y;
            Bs[kq + 2][rowL] = v.z;
            Bs[kq + 3][rowL] = v.w;
        }
        __syncthreads();

#pragma unroll
        for (int kk = 0; kk < BK; kk++) {
            float4 a4 = *(const float4*)&As[kk][ty * 4];
            float4 b4 = *(const float4*)&Bs[kk][tx * 4];
            float av[4] = {a4.x, a4.y, a4.z, a4.w};
            float bv[4] = {b4.x, b4.y, b4.z, b4.w};
#pragma unroll
            for (int i = 0; i < 4; i++)
#pragma unroll
                for (int j = 0; j < 4; j++)
                    acc[i][j] = fmaf(av[i], bv[j], acc[i][j]);
        }
        __syncthreads();
    }

    // Epilogue (per-mode scatter)
#pragma unroll
    for (int i = 0; i < 4; i++) {
        int m = m0 + ty * 4 + i;
        if (m >= M) continue;
#pragma unroll
        for (int j = 0; j < 4; j++) {
            int n = n0 + tx * 4 + j;
            if (n >= N) continue;
            float val = acc[i][j] * alpha;
            if (MODE == MODE_K) {
                int b = m / 196, nn = m - b * 196;
                g_Kt[((size_t)(z * 16 + b) * 960 + n) * 196 + nn] = val;
            } else if (MODE == MODE_V) {
                g_V[(size_t)m * 3840 + (size_t)z * 960 + n] = val;
            } else if (MODE == MODE_Q) {
                g_Q[(size_t)z * ch * 196 + (size_t)m * 196 + n] = val;
            } else if (MODE == MODE_S) {
                int b = z >> 2, h = z & 3;
                g_S[((size_t)b * ch + m) * 3840 + (size_t)h * 960 + n] = val;
            } else if (MODE == MODE_CTX) {
                g_ctx[(size_t)z * 196 * ch + (size_t)m * ch + n] = val;
            } else { // MODE_OUT
                Cg[(size_t)z * 196 * ch + (size_t)m * ch + n] = val;
            }
        }
    }
}

// ---------------------------------------------------------------------------
// Deterministic per-(b,h) sum / sumsq over scores plane [ch][960]
// ---------------------------------------------------------------------------
__global__ __launch_bounds__(256)
void reduce_stats(int ch)
{
    const int z = blockIdx.x;      // b*4 + h
    const int b = z >> 2, h = z & 3;
    const float* base = g_S + (size_t)b * ch * 3840 + (size_t)h * 960;
    const int total = ch * 960;

    float s = 0.f, ss = 0.f;
    for (int idx = threadIdx.x; idx < total; idx += 256) {
        int d = idx / 960;
        int j = idx - d * 960;
        float v = base[(size_t)d * 3840 + j];
        s  += v;
        ss += v * v;
    }
    __shared__ float sh[256], sh2[256];
    sh[threadIdx.x] = s;
    sh2[threadIdx.x] = ss;
    __syncthreads();
    for (int o = 128; o > 0; o >>= 1) {
        if (threadIdx.x < o) {
            sh[threadIdx.x]  += sh[threadIdx.x + o];
            sh2[threadIdx.x] += sh2[threadIdx.x + o];
        }
        __syncthreads();
    }
    if (threadIdx.x == 0) {
        g_stats[2 * z]     = sh[0];
        g_stats[2 * z + 1] = sh2[0];
    }
}

// ---------------------------------------------------------------------------
// InstanceNorm (mean/var per (b,h)) + softmax per row of 960, in place on g_S
// ---------------------------------------------------------------------------
__global__ __launch_bounds__(128)
void softmax_rows(int ch)
{
    const int row = blockIdx.x;          // b*(ch*4) + d*4 + h
    const int h   = row & 3;
    const int t2  = row >> 2;
    const int d   = t2 % ch;
    const int b   = t2 / ch;

    float* p = g_S + (size_t)b * ch * 3840 + (size_t)d * 3840 + (size_t)h * 960;

    const float cnt   = (float)ch * 960.0f;
    const float sum   = g_stats[2 * (b * 4 + h)];
    const float sumsq = g_stats[2 * (b * 4 + h) + 1];
    const float mean  = sum / cnt;
    const float var   = sumsq / cnt - mean * mean;
    const float inv   = rsqrtf(var + 1e-5f);

    const int t = threadIdx.x;
    float v[8];
    float mx = -1e30f;
#pragma unroll
    for (int k = 0; k < 8; k++) {
        int j = t + k * 128;
        v[k] = (j < 960) ? (p[j] - mean) * inv : -1e30f;
        mx = fmaxf(mx, v[k]);
    }

    __shared__ float sh[128];
    sh[t] = mx;
    __syncthreads();
    for (int o = 64; o > 0; o >>= 1) {
        if (t < o) sh[t] = fmaxf(sh[t], sh[t + o]);
        __syncthreads();
    }
    mx = sh[0];
    __syncthreads();

    float lsum = 0.f;
#pragma unroll
    for (int k = 0; k < 8; k++) {
        int j = t + k * 128;
        if (j < 960) {
            v[k] = __expf(v[k] - mx);
            lsum += v[k];
        }
    }
    sh[t] = lsum;
    __syncthreads();
    for (int o = 64; o > 0; o >>= 1) {
        if (t < o) sh[t] += sh[t + o];
        __syncthreads();
    }
    const float rden = 1.0f / sh[0];
#pragma unroll
    for (int k = 0; k < 8; k++) {
        int j = t + k * 128;
        if (j < 960) p[j] = v[k] * rden;
    }
}

// ---------------------------------------------------------------------------
// Launch
// ---------------------------------------------------------------------------
extern "C" void kernel_launch(void* const* d_in, const int* in_sizes, int n_in,
                              void* d_out, int out_size)
{
    // metadata order: emb0..emb3, emb_all, (Wq0,Wo0),(Wq1,Wo1),(Wq2,Wo2),(Wq3,Wo3), Wk, Wv
    const float* emb[4] = {(const float*)d_in[0], (const float*)d_in[1],
                           (const float*)d_in[2], (const float*)d_in[3]};
    const float* emb_all = (const float*)d_in[4];
    const float* Wq[4] = {(const float*)d_in[5], (const float*)d_in[7],
                          (const float*)d_in[9], (const float*)d_in[11]};
    const float* Wo[4] = {(const float*)d_in[6], (const float*)d_in[8],
                          (const float*)d_in[10], (const float*)d_in[12]};
    const float* Wk = (const float*)d_in[13];
    const float* Wv = (const float*)d_in[14];
    float* out = (float*)d_out;

    const float inv_sqrt_kv = 0.032274861218395144f; // 1/sqrt(960)
    const int chs[4] = {64, 128, 256, 512};

    // K^T and V: M=3136 (b,n), N=960 (j), K=960 (k); z = head
    gemm_nt<MODE_K><<<dim3(15, 49, 4), 256>>>(emb_all, Wk, nullptr,
                                              3136, 960, 960, 960, 960, 0, 1.0f);
    gemm_nt<MODE_V><<<dim3(15, 49, 4), 256>>>(emb_all, Wv, nullptr,
                                              3136, 960, 960, 960, 960, 0, 1.0f);

    size_t ooff = 0;
    for (int i = 0; i < 4; i++) {
        const int ch = chs[i];
        const int gm = ch / 64;  // ch is always a multiple of 64

        // Q[b,h]: M=ch (d), N=196 (n), K=ch (c); z = b*4+h
        gemm_nt<MODE_Q><<<dim3(4, gm, 64), 256>>>(Wq[i], emb[i], nullptr,
                                                  ch, 196, ch, ch, ch, ch, 1.0f);

        // scores[b,h]: M=ch (d), N=960 (j), K=196 (n); z = b*4+h
        gemm_nt<MODE_S><<<dim3(15, gm, 64), 256>>>(nullptr, nullptr, nullptr,
                                                   ch, 960, 196, 196, 196, ch,
                                                   inv_sqrt_kv);

        // InstanceNorm stats + softmax (in place on g_S)
        reduce_stats<<<64, 256>>>(ch);
        softmax_rows<<<16 * ch * 4, 128>>>(ch);

        // ctx[b]: M=196 (n), N=ch (d), K=3840 (h*960+j, head-sum fused); z = b
        gemm_nt<MODE_CTX><<<dim3(gm, 4, 16), 256>>>(nullptr, nullptr, nullptr,
                                                    196, ch, 3840, 3840, 3840,
                                                    ch, 0.25f);

        // out[b]: M=196 (n), N=ch (e), K=ch (d); z = b
        gemm_nt<MODE_OUT><<<dim3(gm, 4, 16), 256>>>(nullptr, Wo[i], out + ooff,
                                                    196, ch, ch, ch, ch, ch,
                                                    1.0f);
        ooff += (size_t)16 * 196 * ch;
    }
}

// round 2
// speedup vs baseline: 2.5089x; 2.5089x over previous
#include <cuda_runtime.h>
#include <cuda_bf16.h>
#include <math.h>

// B=16, N=196, KV=960, H=4, chs={64,128,256,512}

#define BM 128
#define BN 64
#define BK 32
#define STAGES 3
#define SAP 40                    // A smem row stride (u32), padded
#define SBP 40
#define A_STAGE (BM*SAP)          // 5120 u32
#define B_STAGE (BN*SBP)          // 2560 u32
#define B_POOL  (STAGES*A_STAGE)
#define SMEM_BYTES ((STAGES*(A_STAGE+B_STAGE))*4)   // 92160

#define MODE_K   0
#define MODE_V   1
#define MODE_Q   2
#define MODE_S   3
#define MODE_CTX 4
#define MODE_OUT 5

// ---------------- packed split-bf16 scratch (u32 = lo<<16 | hi) ----------------
__device__ unsigned g_embap[3136*960];                 // emb_all packed [3136][960]
__device__ unsigned g_Wkp  [4*960*960];                // [h][j][k]
__device__ unsigned g_Wvp  [4*960*960];
__device__ unsigned g_embp [3136*960];                 // 4 embs concatenated
__device__ unsigned g_Wqp  [1392640];                  // 4 scales of [h][d][c]
__device__ unsigned g_Wop  [348160];                   // 4 scales of [e][d]
__device__ unsigned g_Ktp  [(size_t)4*16*960*196];     // [h*16+b][j][n]
__device__ unsigned g_Vp   [(size_t)16*196*3840];      // [b][n][h*960+j]
__device__ unsigned g_Qp   [(size_t)64*512*196];       // [b*4+h][d][n]
__device__ float    g_S    [(size_t)16*512*3840];      // scores fp32 [b][d][h*960+j]
__device__ unsigned g_Pp   [(size_t)16*512*3840];      // probs packed, same layout
__device__ unsigned g_ctxp [(size_t)16*196*512];       // [b][n][d]
__device__ float    g_stats[128];

// ---------------- helpers ----------------
__device__ __forceinline__ unsigned pack2(float v) {
    unsigned short h = __bfloat16_as_ushort(__float2bfloat16_rn(v));
    float hf = __bfloat162float(__ushort_as_bfloat16(h));
    unsigned short l = __bfloat16_as_ushort(__float2bfloat16_rn(v - hf));
    return (unsigned)h | ((unsigned)l << 16);
}

#define MMA_OP(d, a, b) asm volatile( \
    "mma.sync.aligned.m16n8k16.row.col.f32.bf16.bf16.f32 " \
    "{%0,%1,%2,%3},{%4,%5,%6,%7},{%8,%9},{%0,%1,%2,%3};" \
    : "+f"(d[0]), "+f"(d[1]), "+f"(d[2]), "+f"(d[3]) \
    : "r"(a[0]), "r"(a[1]), "r"(a[2]), "r"(a[3]), "r"(b[0]), "r"(b[1]))

__device__ __forceinline__ void cp16(unsigned* sdst, const unsigned* g) {
    unsigned sa = (unsigned)__cvta_generic_to_shared(sdst);
    asm volatile("cp.async.cg.shared.global [%0],[%1],16;\n" :: "r"(sa), "l"(g) : "memory");
}
__device__ __forceinline__ void cp_commit() {
    asm volatile("cp.async.commit_group;\n" ::: "memory");
}

// ---------------- tile loader (gmem packed -> smem, zero-filled) ----------------
__device__ __forceinline__ void load_stage(unsigned* su, int stage,
    const unsigned* __restrict__ A, const unsigned* __restrict__ B,
    int m0, int n0, int k0, int M, int N, int K, int lda, int ldb, int tid)
{
    const int q = tid & 7, r0 = tid >> 3;
#pragma unroll
    for (int it = 0; it < 4; it++) {
        int row = r0 + it * 32;
        int gm = m0 + row;
        unsigned* sdst = su + stage * A_STAGE + row * SAP + q * 4;
        int k = k0 + q * 4;
        if (gm < M && k + 3 < K) {
            cp16(sdst, A + (size_t)gm * lda + k);
        } else {
            uint4 v = make_uint4(0, 0, 0, 0);
            if (gm < M) {
                const unsigned* src = A + (size_t)gm * lda;
                if (k + 0 < K) v.x = src[k + 0];
                if (k + 1 < K) v.y = src[k + 1];
                if (k + 2 < K) v.z = src[k + 2];
                if (k + 3 < K) v.w = src[k + 3];
            }
            *(uint4*)sdst = v;
        }
    }
#pragma unroll
    for (int it = 0; it < 2; it++) {
        int row = r0 + it * 32;
        int gn = n0 + row;
        unsigned* sdst = su + B_POOL + stage * B_STAGE + row * SBP + q * 4;
        int k = k0 + q * 4;
        if (gn < N && k + 3 < K) {
            cp16(sdst, B + (size_t)gn * ldb + k);
        } else {
            uint4 v = make_uint4(0, 0, 0, 0);
            if (gn < N) {
                const unsigned* src = B + (size_t)gn * ldb;
                if (k + 0 < K) v.x = src[k + 0];
                if (k + 1 < K) v.y = src[k + 1];
                if (k + 2 < K) v.z = src[k + 2];
                if (k + 3 < K) v.w = src[k + 3];
            }
            *(uint4*)sdst = v;
        }
    }
}

// ---------------- per-stage MMA compute ----------------
__device__ __forceinline__ void compute_stage(const unsigned* su, int stage,
    float (&acc)[2][4][4], int wm, int wn, int g, int q2)
{
    const unsigned* sa = su + stage * A_STAGE;
    const unsigned* sb = su + B_POOL + stage * B_STAGE;
#pragma unroll
    for (int kk = 0; kk < BK; kk += 16) {
        unsigned ah[2][4], al[2][4], bh[4][2], bl[4][2];
#pragma unroll
        for (int i = 0; i < 2; i++) {
            int r = wm + i * 16 + g;
            uint2 w0 = *(const uint2*)(sa + r * SAP + kk + q2);
            uint2 w1 = *(const uint2*)(sa + (r + 8) * SAP + kk + q2);
            uint2 w2 = *(const uint2*)(sa + r * SAP + kk + 8 + q2);
            uint2 w3 = *(const uint2*)(sa + (r + 8) * SAP + kk + 8 + q2);
            ah[i][0] = __byte_perm(w0.x, w0.y, 0x5410); al[i][0] = __byte_perm(w0.x, w0.y, 0x7632);
            ah[i][1] = __byte_perm(w1.x, w1.y, 0x5410); al[i][1] = __byte_perm(w1.x, w1.y, 0x7632);
            ah[i][2] = __byte_perm(w2.x, w2.y, 0x5410); al[i][2] = __byte_perm(w2.x, w2.y, 0x7632);
            ah[i][3] = __byte_perm(w3.x, w3.y, 0x5410); al[i][3] = __byte_perm(w3.x, w3.y, 0x7632);
        }
#pragma unroll
        for (int j = 0; j < 4; j++) {
            int c = wn + j * 8 + g;
            uint2 u0 = *(const uint2*)(sb + c * SBP + kk + q2);
            uint2 u1 = *(const uint2*)(sb + c * SBP + kk + 8 + q2);
            bh[j][0] = __byte_perm(u0.x, u0.y, 0x5410); bl[j][0] = __byte_perm(u0.x, u0.y, 0x7632);
            bh[j][1] = __byte_perm(u1.x, u1.y, 0x5410); bl[j][1] = __byte_perm(u1.x, u1.y, 0x7632);
        }
#pragma unroll
        for (int i = 0; i < 2; i++)
#pragma unroll
            for (int j = 0; j < 4; j++) {
                MMA_OP(acc[i][j], ah[i], bh[j]);
                MMA_OP(acc[i][j], ah[i], bl[j]);
                MMA_OP(acc[i][j], al[i], bh[j]);
            }
    }
}

// ---------------- mode-specific pair store ----------------
template <int MODE>
__device__ __forceinline__ void store2(int m, int n, float v0, float v1,
                                       int M, int N, int ch, int z, float* Cg)
{
    if (m >= M || n >= N) return;
    if (MODE == MODE_K) {            // z = h*16+b, out [z][j=m][n]
        unsigned* p = g_Ktp + (size_t)z * 188160 + (size_t)m * 196 + n;
        *(uint2*)p = make_uint2(pack2(v0), pack2(v1));
    } else if (MODE == MODE_V) {     // z = head, out [m=(b,n)][z*960+j]
        unsigned* p = g_Vp + (size_t)m * 3840 + z * 960 + n;
        *(uint2*)p = make_uint2(pack2(v0), pack2(v1));
    } else if (MODE == MODE_Q) {     // z = b*4+h, out [z][d=m][n]
        unsigned* p = g_Qp + (size_t)z * ch * 196 + (size_t)m * 196 + n;
        *(uint2*)p = make_uint2(pack2(v0), pack2(v1));
    } else if (MODE == MODE_S) {     // z = b*4+h, fp32 scores
        float* p = g_S + ((size_t)(z >> 2) * ch + m) * 3840 + (z & 3) * 960 + n;
        *(float2*)p = make_float2(v0, v1);
    } else if (MODE == MODE_CTX) {   // z = b, out [z][n=m][d]
        unsigned* p = g_ctxp + (size_t)z * 196 * ch + (size_t)m * ch + n;
        *(uint2*)p = make_uint2(pack2(v0), pack2(v1));
    } else {                         // z = b, fp32 final out
        float* p = Cg + (size_t)z * 196 * ch + (size_t)m * ch + n;
        *(float2*)p = make_float2(v0, v1);
    }
}

// ---------------- GEMM: C = alpha * A[M][K] * B[N][K]^T ----------------
template <int MODE>
__global__ __launch_bounds__(256, 2)
void gemm_p(int M, int N, int K, int lda, int ldb, int ch, float alpha,
            int aoff, int boff, float* Cg)
{
    extern __shared__ unsigned su[];
    const int z = blockIdx.z;

    const unsigned* A;
    const unsigned* B;
    if (MODE == MODE_K) {           // A=Wk[h] [960][960], B=emb_all[b] [196][960]
        A = g_Wkp + (size_t)(z >> 4) * 921600;
        B = g_embap + (size_t)(z & 15) * 188160;
    } else if (MODE == MODE_V) {    // A=emb_all [3136][960], B=Wv[h]
        A = g_embap;
        B = g_Wvp + (size_t)z * 921600;
    } else if (MODE == MODE_Q) {    // A=Wq[h] [ch][ch], B=emb[b] [196][ch]
        A = g_Wqp + aoff + (size_t)(z & 3) * ch * ch;
        B = g_embp + boff + (size_t)(z >> 2) * 196 * ch;
    } else if (MODE == MODE_S) {    // A=Q[z] [ch][196], B=Kt[h*16+b] [960][196]
        A = g_Qp + (size_t)z * ch * 196;
        B = g_Ktp + (size_t)((z & 3) * 16 + (z >> 2)) * 188160;
    } else if (MODE == MODE_CTX) {  // A=V[b] [196][3840], B=probs[b] [ch][3840]
        A = g_Vp + (size_t)z * 752640;
        B = g_Pp + (size_t)z * ch * 3840;
    } else {                        // A=ctx[b] [196][ch], B=Wo [ch][ch]
        A = g_ctxp + (size_t)z * 196 * ch;
        B = g_Wop + boff;
    }

    const int m0 = blockIdx.y * BM, n0 = blockIdx.x * BN;
    const int tid = threadIdx.x;
    const int warp = tid >> 5, lane = tid & 31;
    const int wm = (warp >> 1) * 32, wn = (warp & 1) * 32;
    const int g = lane >> 2, q2 = (lane & 3) * 2;

    float acc[2][4][4];
#pragma unroll
    for (int i = 0; i < 2; i++)
#pragma unroll
        for (int j = 0; j < 4; j++)
#pragma unroll
            for (int r = 0; r < 4; r++) acc[i][j][r] = 0.0f;

    const int nch = (K + BK - 1) / BK;
    const int pre = (STAGES - 1 < nch) ? STAGES - 1 : nch;
    for (int s = 0; s < pre; s++) {
        load_stage(su, s, A, B, m0, n0, s * BK, M, N, K, lda, ldb, tid);
        cp_commit();
    }
    for (int c = 0; c < nch; c++) {
        if (c + STAGES - 1 < nch) {
            load_stage(su, (c + STAGES - 1) % STAGES, A, B, m0, n0,
                       (c + STAGES - 1) * BK, M, N, K, lda, ldb, tid);
            cp_commit();
        }
        int issued = (c + STAGES < nch) ? c + STAGES : nch;
        int pend = issued - 1 - c;
        if (pend >= 2)      asm volatile("cp.async.wait_group 2;\n" ::: "memory");
        else if (pend == 1) asm volatile("cp.async.wait_group 1;\n" ::: "memory");
        else                asm volatile("cp.async.wait_group 0;\n" ::: "memory");
        __syncthreads();
        compute_stage(su, c % STAGES, acc, wm, wn, g, q2);
        __syncthreads();
    }

#pragma unroll
    for (int i = 0; i < 2; i++) {
        int m = m0 + wm + i * 16 + g;
#pragma unroll
        for (int j = 0; j < 4; j++) {
            int n = n0 + wn + j * 8 + q2;
            store2<MODE>(m,     n, acc[i][j][0] * alpha, acc[i][j][1] * alpha, M, N, ch, z, Cg);
            store2<MODE>(m + 8, n, acc[i][j][2] * alpha, acc[i][j][3] * alpha, M, N, ch, z, Cg);
        }
    }
}

// ---------------- fp32 -> packed split-bf16 conversion ----------------
__global__ void pack_f32(const float* __restrict__ in, int which, int off, int n)
{
    int i = blockIdx.x * 256 + threadIdx.x;
    if (i >= n) return;
    unsigned* dst;
    switch (which) {
        case 0: dst = g_embap; break;
        case 1: dst = g_Wkp;   break;
        case 2: dst = g_Wvp;   break;
        case 3: dst = g_embp;  break;
        case 4: dst = g_Wqp;   break;
        default: dst = g_Wop;  break;
    }
    dst[off + i] = pack2(in[i]);
}

// ---------------- InstanceNorm stats (deterministic) ----------------
__global__ __launch_bounds__(256)
void reduce_stats(int ch)
{
    const int z = blockIdx.x;            // b*4 + h
    const int b = z >> 2, h = z & 3;
    const float* base = g_S + (size_t)b * ch * 3840 + (size_t)h * 960;
    const int total = ch * 960;

    float s = 0.f, ss = 0.f;
    for (int idx = threadIdx.x; idx < total; idx += 256) {
        int d = idx / 960;
        int j = idx - d * 960;
        float v = base[(size_t)d * 3840 + j];
        s += v; ss += v * v;
    }
    __shared__ float sh[256], sh2[256];
    sh[threadIdx.x] = s; sh2[threadIdx.x] = ss;
    __syncthreads();
    for (int o = 128; o > 0; o >>= 1) {
        if (threadIdx.x < o) {
            sh[threadIdx.x]  += sh[threadIdx.x + o];
            sh2[threadIdx.x] += sh2[threadIdx.x + o];
        }
        __syncthreads();
    }
    if (threadIdx.x == 0) { g_stats[2*z] = sh[0]; g_stats[2*z+1] = sh2[0]; }
}

// ---------------- norm + softmax, writes packed probs ----------------
__global__ __launch_bounds__(128)
void softmax_rows(int ch)
{
    const int row = blockIdx.x;           // b*(ch*4) + d*4 + h
    const int h = row & 3;
    const int t2 = row >> 2;
    const int d = t2 % ch;
    const int b = t2 / ch;

    const size_t off = (size_t)b * ch * 3840 + (size_t)d * 3840 + (size_t)h * 960;
    const float* p = g_S + off;
    unsigned* po = g_Pp + off;

    const float cnt = (float)ch * 960.0f;
    const float sum = g_stats[2 * (b * 4 + h)];
    const float sumsq = g_stats[2 * (b * 4 + h) + 1];
    const float mean = sum / cnt;
    const float var = sumsq / cnt - mean * mean;
    const float inv = rsqrtf(var + 1e-5f);

    const int t = threadIdx.x;
    float v[8];
    float mx = -1e30f;
#pragma unroll
    for (int k = 0; k < 8; k++) {
        int j = t + k * 128;
        v[k] = (j < 960) ? (p[j] - mean) * inv : -1e30f;
        mx = fmaxf(mx, v[k]);
    }
    __shared__ float sh[128];
    sh[t] = mx; __syncthreads();
    for (int o = 64; o > 0; o >>= 1) {
        if (t < o) sh[t] = fmaxf(sh[t], sh[t + o]);
        __syncthreads();
    }
    mx = sh[0]; __syncthreads();

    float lsum = 0.f;
#pragma unroll
    for (int k = 0; k < 8; k++) {
        int j = t + k * 128;
        if (j < 960) { v[k] = __expf(v[k] - mx); lsum += v[k]; }
    }
    sh[t] = lsum; __syncthreads();
    for (int o = 64; o > 0; o >>= 1) {
        if (t < o) sh[t] += sh[t + o];
        __syncthreads();
    }
    const float rden = 1.0f / sh[0];
#pragma unroll
    for (int k = 0; k < 8; k++) {
        int j = t + k * 128;
        if (j < 960) po[j] = pack2(v[k] * rden);
    }
}

// ---------------- launch ----------------
extern "C" void kernel_launch(void* const* d_in, const int* in_sizes, int n_in,
                              void* d_out, int out_size)
{
    const float* emb[4] = {(const float*)d_in[0], (const float*)d_in[1],
                           (const float*)d_in[2], (const float*)d_in[3]};
    const float* emb_all = (const float*)d_in[4];
    const float* Wq[4] = {(const float*)d_in[5], (const float*)d_in[7],
                          (const float*)d_in[9], (const float*)d_in[11]};
    const float* Wo[4] = {(const float*)d_in[6], (const float*)d_in[8],
                          (const float*)d_in[10], (const float*)d_in[12]};
    const float* Wk = (const float*)d_in[13];
    const float* Wv = (const float*)d_in[14];
    float* out = (float*)d_out;

    cudaFuncSetAttribute((const void*)gemm_p<MODE_K>,   cudaFuncAttributeMaxDynamicSharedMemorySize, SMEM_BYTES);
    cudaFuncSetAttribute((const void*)gemm_p<MODE_V>,   cudaFuncAttributeMaxDynamicSharedMemorySize, SMEM_BYTES);
    cudaFuncSetAttribute((const void*)gemm_p<MODE_Q>,   cudaFuncAttributeMaxDynamicSharedMemorySize, SMEM_BYTES);
    cudaFuncSetAttribute((const void*)gemm_p<MODE_S>,   cudaFuncAttributeMaxDynamicSharedMemorySize, SMEM_BYTES);
    cudaFuncSetAttribute((const void*)gemm_p<MODE_CTX>, cudaFuncAttributeMaxDynamicSharedMemorySize, SMEM_BYTES);
    cudaFuncSetAttribute((const void*)gemm_p<MODE_OUT>, cudaFuncAttributeMaxDynamicSharedMemorySize, SMEM_BYTES);

    const float inv_sqrt_kv = 0.032274861218395144f;  // 1/sqrt(960)
    const int chs[4] = {64, 128, 256, 512};
    const int eoff[4] = {0, 200704, 602112, 1405184};
    const int qoff[4] = {0, 16384, 81920, 344064};
    const int woff[4] = {0, 4096, 20480, 86016};

    // pack all fp32 inputs into split-bf16
    auto P = [](const float* s, int which, int off, int n) {
        pack_f32<<<(n + 255) / 256, 256>>>(s, which, off, n);
    };
    P(emb_all, 0, 0, 3010560);
    P(Wk, 1, 0, 3686400);
    P(Wv, 2, 0, 3686400);
    for (int i = 0; i < 4; i++) {
        P(emb[i], 3, eoff[i], 16 * 196 * chs[i]);
        P(Wq[i],  4, qoff[i], 4 * chs[i] * chs[i]);
        P(Wo[i],  5, woff[i], chs[i] * chs[i]);
    }

    // Kt[h,b][j][n] : M=960(j), N=196(n), K=960 ; z = h*16+b
    gemm_p<MODE_K><<<dim3(4, 8, 64), 256, SMEM_BYTES>>>(960, 196, 960, 960, 960, 0, 1.0f, 0, 0, nullptr);
    // V[b,n][h*960+j] : M=3136, N=960, K=960 ; z = head
    gemm_p<MODE_V><<<dim3(15, 25, 4), 256, SMEM_BYTES>>>(3136, 960, 960, 960, 960, 0, 1.0f, 0, 0, nullptr);

    size_t ooff = 0;
    for (int i = 0; i < 4; i++) {
        const int ch = chs[i];
        const int gy = (ch + BM - 1) / BM;
        const int gn = ch / BN;

        // Q[z][d][n] : M=ch, N=196, K=ch ; z = b*4+h
        gemm_p<MODE_Q><<<dim3(4, gy, 64), 256, SMEM_BYTES>>>(ch, 196, ch, ch, ch, ch, 1.0f, qoff[i], eoff[i], nullptr);
        // scores : M=ch, N=960, K=196 ; z = b*4+h
        gemm_p<MODE_S><<<dim3(15, gy, 64), 256, SMEM_BYTES>>>(ch, 960, 196, 196, 196, ch, inv_sqrt_kv, 0, 0, nullptr);

        reduce_stats<<<64, 256>>>(ch);
        softmax_rows<<<16 * ch * 4, 128>>>(ch);

        // ctx[b][n][d] : M=196, N=ch, K=3840 ; z = b  (head-mean via alpha)
        gemm_p<MODE_CTX><<<dim3(gn, 2, 16), 256, SMEM_BYTES>>>(196, ch, 3840, 3840, 3840, ch, 0.25f, 0, 0, nullptr);
        // out[b][n][e] : M=196, N=ch, K=ch ; z = b
        gemm_p<MODE_OUT><<<dim3(gn, 2, 16), 256, SMEM_BYTES>>>(196, ch, ch, ch, ch, ch, 1.0f, 0, woff[i], out + ooff);
        ooff += (size_t)16 * 196 * ch;
    }
}

// round 8
// speedup vs baseline: 2.5668x; 1.0231x over previous
#include <cuda_runtime.h>
#include <cuda_bf16.h>
#include <cstdint>
#include <math.h>

// B=16, N=196, KV=960, H=4, chs={64,128,256,512}

#define BM 128
#define BN 64
#define BK 32
#define STAGES 2
#define SAP 40                    // A smem row stride (u32), padded
#define SBP 40
#define A_STAGE (BM*SAP)          // 5120 u32
#define B_STAGE (BN*SBP)          // 2560 u32
#define B_POOL  (STAGES*A_STAGE)
#define SMEM_BYTES ((STAGES*(A_STAGE+B_STAGE))*4)   // 61440

#define MODE_K   0
#define MODE_V   1
#define MODE_Q   2
#define MODE_S   3
#define MODE_CTX 4
#define MODE_OUT 5

// ---------------- packed split-bf16 scratch (u32 = lo<<16 | hi) ----------------
__device__ unsigned g_embap[3136*960];                 // emb_all packed [3136][960]
__device__ unsigned g_Wkp  [4*960*960];                // [h][j][k]
__device__ unsigned g_Wvp  [4*960*960];
__device__ unsigned g_embp [3136*960];                 // 4 embs concatenated
__device__ unsigned g_Wqp  [1392640];                  // 4 scales of [h][d][c]
__device__ unsigned g_Wop  [348160];                   // 4 scales of [e][d]
__device__ unsigned g_Ktp  [(size_t)4*16*960*196];     // [h*16+b][j][n]
__device__ unsigned g_Vp   [(size_t)16*196*3840];      // [b][n][h*960+j]
__device__ unsigned g_Qp   [(size_t)64*512*196];       // [b*4+h][d][n]  (max ch)
__device__ float    g_S    [(size_t)16*512*3840];      // scores fp32 [b][d][h*960+j]
__device__ unsigned g_Pp   [(size_t)16*512*3840];      // probs packed, same layout
__device__ unsigned g_ctxp [(size_t)16*196*512];       // [b][n][d]
__device__ float    g_stats[128];

// ---------------- helpers ----------------
__device__ __forceinline__ unsigned pack2(float v) {
    unsigned short h = __bfloat16_as_ushort(__float2bfloat16_rn(v));
    float hf = __bfloat162float(__ushort_as_bfloat16(h));
    unsigned short l = __bfloat16_as_ushort(__float2bfloat16_rn(v - hf));
    return (unsigned)h | ((unsigned)l << 16);
}

#define MMA_OP(d, a, b) asm volatile( \
    "mma.sync.aligned.m16n8k16.row.col.f32.bf16.bf16.f32 " \
    "{%0,%1,%2,%3},{%4,%5,%6,%7},{%8,%9},{%0,%1,%2,%3};" \
    : "+f"(d[0]), "+f"(d[1]), "+f"(d[2]), "+f"(d[3]) \
    : "r"(a[0]), "r"(a[1]), "r"(a[2]), "r"(a[3]), "r"(b[0]), "r"(b[1]))

__device__ __forceinline__ void cp16(unsigned* sdst, const unsigned* g) {
    unsigned sa = (unsigned)__cvta_generic_to_shared(sdst);
    asm volatile("cp.async.cg.shared.global [%0],[%1],16;\n" :: "r"(sa), "l"(g) : "memory");
}
__device__ __forceinline__ void cp_commit() {
    asm volatile("cp.async.commit_group;\n" ::: "memory");
}

// ---------------- tile loader (gmem packed -> smem, zero-filled) ----------------
__device__ __forceinline__ void load_stage(unsigned* su, int stage,
    const unsigned* __restrict__ A, const unsigned* __restrict__ B,
    int m0, int n0, int k0, int M, int N, int K, int lda, int ldb, int tid)
{
    const int q = tid & 7, r0 = tid >> 3;
#pragma unroll
    for (int it = 0; it < 4; it++) {
        int row = r0 + it * 32;
        int gm = m0 + row;
        unsigned* sdst = su + stage * A_STAGE + row * SAP + q * 4;
        int k = k0 + q * 4;
        if (gm < M && k + 3 < K) {
            cp16(sdst, A + (size_t)gm * lda + k);
        } else {
            uint4 v = make_uint4(0, 0, 0, 0);
            if (gm < M) {
                const unsigned* src = A + (size_t)gm * lda;
                if (k + 0 < K) v.x = src[k + 0];
                if (k + 1 < K) v.y = src[k + 1];
                if (k + 2 < K) v.z = src[k + 2];
                if (k + 3 < K) v.w = src[k + 3];
            }
            *(uint4*)sdst = v;
        }
    }
#pragma unroll
    for (int it = 0; it < 2; it++) {
        int row = r0 + it * 32;
        int gn = n0 + row;
        unsigned* sdst = su + B_POOL + stage * B_STAGE + row * SBP + q * 4;
        int k = k0 + q * 4;
        if (gn < N && k + 3 < K) {
            cp16(sdst, B + (size_t)gn * ldb + k);
        } else {
            uint4 v = make_uint4(0, 0, 0, 0);
            if (gn < N) {
                const unsigned* src = B + (size_t)gn * ldb;
                if (k + 0 < K) v.x = src[k + 0];
                if (k + 1 < K) v.y = src[k + 1];
                if (k + 2 < K) v.z = src[k + 2];
                if (k + 3 < K) v.w = src[k + 3];
            }
            *(uint4*)sdst = v;
        }
    }
}

// ---------------- per-stage MMA compute ----------------
__device__ __forceinline__ void compute_stage(const unsigned* su, int stage,
    float (&acc)[2][4][4], int wm, int wn, int g, int q2)
{
    const unsigned* sa = su + stage * A_STAGE;
    const unsigned* sb = su + B_POOL + stage * B_STAGE;
#pragma unroll
    for (int kk = 0; kk < BK; kk += 16) {
        unsigned ah[2][4], al[2][4], bh[4][2], bl[4][2];
#pragma unroll
        for (int i = 0; i < 2; i++) {
            int r = wm + i * 16 + g;
            uint2 w0 = *(const uint2*)(sa + r * SAP + kk + q2);
            uint2 w1 = *(const uint2*)(sa + (r + 8) * SAP + kk + q2);
            uint2 w2 = *(const uint2*)(sa + r * SAP + kk + 8 + q2);
            uint2 w3 = *(const uint2*)(sa + (r + 8) * SAP + kk + 8 + q2);
            ah[i][0] = __byte_perm(w0.x, w0.y, 0x5410); al[i][0] = __byte_perm(w0.x, w0.y, 0x7632);
            ah[i][1] = __byte_perm(w1.x, w1.y, 0x5410); al[i][1] = __byte_perm(w1.x, w1.y, 0x7632);
            ah[i][2] = __byte_perm(w2.x, w2.y, 0x5410); al[i][2] = __byte_perm(w2.x, w2.y, 0x7632);
            ah[i][3] = __byte_perm(w3.x, w3.y, 0x5410); al[i][3] = __byte_perm(w3.x, w3.y, 0x7632);
        }
#pragma unroll
        for (int j = 0; j < 4; j++) {
            int c = wn + j * 8 + g;
            uint2 u0 = *(const uint2*)(sb + c * SBP + kk + q2);
            uint2 u1 = *(const uint2*)(sb + c * SBP + kk + 8 + q2);
            bh[j][0] = __byte_perm(u0.x, u0.y, 0x5410); bl[j][0] = __byte_perm(u0.x, u0.y, 0x7632);
            bh[j][1] = __byte_perm(u1.x, u1.y, 0x5410); bl[j][1] = __byte_perm(u1.x, u1.y, 0x7632);
        }
#pragma unroll
        for (int i = 0; i < 2; i++)
#pragma unroll
            for (int j = 0; j < 4; j++) {
                MMA_OP(acc[i][j], ah[i], bh[j]);
                MMA_OP(acc[i][j], ah[i], bl[j]);
                MMA_OP(acc[i][j], al[i], bh[j]);
            }
    }
}

// ---------------- mode-specific pair store ----------------
template <int MODE>
__device__ __forceinline__ void store2(int m, int n, float v0, float v1,
                                       int M, int N, int ch, int z, float* Cg)
{
    if (m >= M || n >= N) return;
    if (MODE == MODE_K) {            // z = h*16+b, out [z][j=m][n]
        unsigned* p = g_Ktp + (size_t)z * 188160 + (size_t)m * 196 + n;
        *(uint2*)p = make_uint2(pack2(v0), pack2(v1));
    } else if (MODE == MODE_V) {     // z = head, out [m=(b,n)][z*960+j]
        unsigned* p = g_Vp + (size_t)m * 3840 + z * 960 + n;
        *(uint2*)p = make_uint2(pack2(v0), pack2(v1));
    } else if (MODE == MODE_Q) {     // z = b*4+h, out [z][d=m][n]
        unsigned* p = g_Qp + (size_t)z * ch * 196 + (size_t)m * 196 + n;
        *(uint2*)p = make_uint2(pack2(v0), pack2(v1));
    } else if (MODE == MODE_S) {     // z = b*4+h, fp32 scores
        float* p = g_S + ((size_t)(z >> 2) * ch + m) * 3840 + (z & 3) * 960 + n;
        *(float2*)p = make_float2(v0, v1);
    } else if (MODE == MODE_CTX) {   // z = b, out [z][n=m][d]
        unsigned* p = g_ctxp + (size_t)z * 196 * ch + (size_t)m * ch + n;
        *(uint2*)p = make_uint2(pack2(v0), pack2(v1));
    } else {                         // z = b, fp32 final out
        float* p = Cg + (size_t)z * 196 * ch + (size_t)m * ch + n;
        *(float2*)p = make_float2(v0, v1);
    }
}

// ---------------- GEMM: C = alpha * A[M][K] * B[N][K]^T ----------------
template <int MODE>
__global__ __launch_bounds__(256, 2)
void gemm_p(int M, int N, int K, int lda, int ldb, int ch, float alpha,
            int aoff, int boff, float* Cg)
{
    extern __shared__ unsigned su[];
    const int z = blockIdx.z;

    const unsigned* A;
    const unsigned* B;
    if (MODE == MODE_K) {           // A=Wk[h] [960][960], B=emb_all[b] [196][960]
        A = g_Wkp + (size_t)(z >> 4) * 921600;
        B = g_embap + (size_t)(z & 15) * 188160;
    } else if (MODE == MODE_V) {    // A=emb_all [3136][960], B=Wv[h]
        A = g_embap;
        B = g_Wvp + (size_t)z * 921600;
    } else if (MODE == MODE_Q) {    // A=Wq[h] [ch][ch], B=emb[b] [196][ch]
        A = g_Wqp + aoff + (size_t)(z & 3) * ch * ch;
        B = g_embp + boff + (size_t)(z >> 2) * 196 * ch;
    } else if (MODE == MODE_S) {    // A=Q[z] [ch][196], B=Kt[h*16+b] [960][196]
        A = g_Qp + (size_t)z * ch * 196;
        B = g_Ktp + (size_t)((z & 3) * 16 + (z >> 2)) * 188160;
    } else if (MODE == MODE_CTX) {  // A=V[b] [196][3840], B=probs[b] [ch][3840]
        A = g_Vp + (size_t)z * 752640;
        B = g_Pp + (size_t)z * ch * 3840;
    } else {                        // A=ctx[b] [196][ch], B=Wo [ch][ch]
        A = g_ctxp + (size_t)z * 196 * ch;
        B = g_Wop + boff;
    }

    const int m0 = blockIdx.y * BM, n0 = blockIdx.x * BN;
    const int tid = threadIdx.x;
    const int warp = tid >> 5, lane = tid & 31;
    const int wm = (warp >> 1) * 32, wn = (warp & 1) * 32;
    const int g = lane >> 2, q2 = (lane & 3) * 2;

    float acc[2][4][4];
#pragma unroll
    for (int i = 0; i < 2; i++)
#pragma unroll
        for (int j = 0; j < 4; j++)
#pragma unroll
            for (int r = 0; r < 4; r++) acc[i][j][r] = 0.0f;

    const int nch = (K + BK - 1) / BK;
    const int pre = (STAGES - 1 < nch) ? STAGES - 1 : nch;
    for (int s = 0; s < pre; s++) {
        load_stage(su, s, A, B, m0, n0, s * BK, M, N, K, lda, ldb, tid);
        cp_commit();
    }
    for (int c = 0; c < nch; c++) {
        if (c + STAGES - 1 < nch) {
            load_stage(su, (c + STAGES - 1) % STAGES, A, B, m0, n0,
                       (c + STAGES - 1) * BK, M, N, K, lda, ldb, tid);
            cp_commit();
        }
        int issued = (c + STAGES < nch) ? c + STAGES : nch;
        int pend = issued - 1 - c;
        if (pend >= 1) asm volatile("cp.async.wait_group 1;\n" ::: "memory");
        else           asm volatile("cp.async.wait_group 0;\n" ::: "memory");
        __syncthreads();
        compute_stage(su, c % STAGES, acc, wm, wn, g, q2);
        __syncthreads();
    }

    // Epilogue (per-mode scatter)
#pragma unroll
    for (int i = 0; i < 2; i++) {
        int m = m0 + wm + i * 16 + g;
#pragma unroll
        for (int j = 0; j < 4; j++) {
            int n = n0 + wn + j * 8 + q2;
            store2<MODE>(m,     n, acc[i][j][0] * alpha, acc[i][j][1] * alpha, M, N, ch, z, Cg);
            store2<MODE>(m + 8, n, acc[i][j][2] * alpha, acc[i][j][3] * alpha, M, N, ch, z, Cg);
        }
    }
}

// ---------------- fp32 -> packed split-bf16 conversion ----------------
__global__ void pack_f32(const float* __restrict__ in, int which, int off, int n)
{
    int i = blockIdx.x * 256 + threadIdx.x;
    if (i >= n) return;
    unsigned* dst;
    switch (which) {
        case 0: dst = g_embap; break;
        case 1: dst = g_Wkp;   break;
        case 2: dst = g_Wvp;   break;
        case 3: dst = g_embp;  break;
        case 4: dst = g_Wqp;   break;
        default: dst = g_Wop;  break;
    }
    dst[off + i] = pack2(in[i]);
}

// ---------------- InstanceNorm stats (deterministic) ----------------
__global__ __launch_bounds__(256)
void reduce_stats(int ch)
{
    const int z = blockIdx.x;            // b*4 + h
    const int b = z >> 2, h = z & 3;
    const float* base = g_S + (size_t)b * ch * 3840 + (size_t)h * 960;
    const int total = ch * 960;

    float s = 0.f, ss = 0.f;
    for (int idx = threadIdx.x; idx < total; idx += 256) {
        int d = idx / 960;
        int j = idx - d * 960;
        float v = base[(size_t)d * 3840 + j];
        s += v; ss += v * v;
    }
    __shared__ float sh[256], sh2[256];
    sh[threadIdx.x] = s; sh2[threadIdx.x] = ss;
    __syncthreads();
    for (int o = 128; o > 0; o >>= 1) {
        if (threadIdx.x < o) {
            sh[threadIdx.x]  += sh[threadIdx.x + o];
            sh2[threadIdx.x] += sh2[threadIdx.x + o];
        }
        __syncthreads();
    }
    if (threadIdx.x == 0) { g_stats[2*z] = sh[0]; g_stats[2*z+1] = sh2[0]; }
}

// ---------------- norm + softmax, writes packed probs ----------------
__global__ __launch_bounds__(128)
void softmax_rows(int ch)
{
    const int row = blockIdx.x;           // b*(ch*4) + d*4 + h
    const int h = row & 3;
    const int t2 = row >> 2;
    const int d = t2 % ch;
    const int b = t2 / ch;

    const size_t off = (size_t)b * ch * 3840 + (size_t)d * 3840 + (size_t)h * 960;
    const float* p = g_S + off;
    unsigned* po = g_Pp + off;

    const float cnt = (float)ch * 960.0f;
    const float sum = g_stats[2 * (b * 4 + h)];
    const float sumsq = g_stats[2 * (b * 4 + h) + 1];
    const float mean = sum / cnt;
    const float var = sumsq / cnt - mean * mean;
    const float inv = rsqrtf(var + 1e-5f);

    const int t = threadIdx.x;
    float v[8];
    float mx = -1e30f;
#pragma unroll
    for (int k = 0; k < 8; k++) {
        int j = t + k * 128;
        v[k] = (j < 960) ? (p[j] - mean) * inv : -1e30f;
        mx = fmaxf(mx, v[k]);
    }
    __shared__ float sh[128];
    sh[t] = mx; __syncthreads();
    for (int o = 64; o > 0; o >>= 1) {
        if (t < o) sh[t] = fmaxf(sh[t], sh[t + o]);
        __syncthreads();
    }
    mx = sh[0]; __syncthreads();

    float lsum = 0.f;
#pragma unroll
    for (int k = 0; k < 8; k++) {
        int j = t + k * 128;
        if (j < 960) { v[k] = __expf(v[k] - mx); lsum += v[k]; }
    }
    sh[t] = lsum; __syncthreads();
    for (int o = 64; o > 0; o >>= 1) {
        if (t < o) sh[t] += sh[t + o];
        __syncthreads();
    }
    const float rden = 1.0f / sh[0];
#pragma unroll
    for (int k = 0; k < 8; k++) {
        int j = t + k * 128;
        if (j < 960) po[j] = pack2(v[k] * rden);
    }
}

// ---------------- launch ----------------
extern "C" void kernel_launch(void* const* d_in, const int* in_sizes, int n_in,
                              void* d_out, int out_size)
{
    const float* emb[4] = {(const float*)d_in[0], (const float*)d_in[1],
                           (const float*)d_in[2], (const float*)d_in[3]};
    const float* emb_all = (const float*)d_in[4];
    const float* Wq[4] = {(const float*)d_in[5], (const float*)d_in[7],
                          (const float*)d_in[9], (const float*)d_in[11]};
    const float* Wo[4] = {(const float*)d_in[6], (const float*)d_in[8],
                          (const float*)d_in[10], (const float*)d_in[12]};
    const float* Wk = (const float*)d_in[13];
    const float* Wv = (const float*)d_in[14];
    float* out = (float*)d_out;

    cudaFuncSetAttribute((const void*)gemm_p<MODE_K>,   cudaFuncAttributeMaxDynamicSharedMemorySize, SMEM_BYTES);
    cudaFuncSetAttribute((const void*)gemm_p<MODE_V>,   cudaFuncAttributeMaxDynamicSharedMemorySize, SMEM_BYTES);
    cudaFuncSetAttribute((const void*)gemm_p<MODE_Q>,   cudaFuncAttributeMaxDynamicSharedMemorySize, SMEM_BYTES);
    cudaFuncSetAttribute((const void*)gemm_p<MODE_S>,   cudaFuncAttributeMaxDynamicSharedMemorySize, SMEM_BYTES);
    cudaFuncSetAttribute((const void*)gemm_p<MODE_CTX>, cudaFuncAttributeMaxDynamicSharedMemorySize, SMEM_BYTES);
    cudaFuncSetAttribute((const void*)gemm_p<MODE_OUT>, cudaFuncAttributeMaxDynamicSharedMemorySize, SMEM_BYTES);

    const float inv_sqrt_kv = 0.032274861218395144f;  // 1/sqrt(960)
    const int chs[4] = {64, 128, 256, 512};
    const int eoff[4] = {0, 200704, 602112, 1405184};
    const int qoff[4] = {0, 16384, 81920, 344064};
    const int woff[4] = {0, 4096, 20480, 86016};

    // pack all fp32 inputs into split-bf16
    auto P = [](const float* s, int which, int off, int n) {
        pack_f32<<<(n + 255) / 256, 256>>>(s, which, off, n);
    };
    P(emb_all, 0, 0, 3010560);
    P(Wk, 1, 0, 3686400);
    P(Wv, 2, 0, 3686400);
    for (int i = 0; i < 4; i++) {
        P(emb[i], 3, eoff[i], 16 * 196 * chs[i]);
        P(Wq[i],  4, qoff[i], 4 * chs[i] * chs[i]);
        P(Wo[i],  5, woff[i], chs[i] * chs[i]);
    }

    // Kt[h,b][j][n] : M=960(j), N=196(n), K=960 ; z = h*16+b
    gemm_p<MODE_K><<<dim3(4, 8, 64), 256, SMEM_BYTES>>>(960, 196, 960, 960, 960, 0, 1.0f, 0, 0, nullptr);
    // V[b,n][h*960+j] : M=3136, N=960, K=960 ; z = head
    gemm_p<MODE_V><<<dim3(15, 25, 4), 256, SMEM_BYTES>>>(3136, 960, 960, 960, 960, 0, 1.0f, 0, 0, nullptr);

    size_t ooff = 0;
    for (int i = 0; i < 4; i++) {
        const int ch = chs[i];
        const int gy = (ch + BM - 1) / BM;
        const int gn = ch / BN;

        // Q[z][d][n] : M=ch, N=196, K=ch ; z = b*4+h
        gemm_p<MODE_Q><<<dim3(4, gy, 64), 256, SMEM_BYTES>>>(ch, 196, ch, ch, ch, ch, 1.0f, qoff[i], eoff[i], nullptr);
        // scores : M=ch, N=960, K=196 ; z = b*4+h
        gemm_p<MODE_S><<<dim3(15, gy, 64), 256, SMEM_BYTES>>>(ch, 960, 196, 196, 196, ch, inv_sqrt_kv, 0, 0, nullptr);

        reduce_stats<<<64, 256>>>(ch);
        softmax_rows<<<16 * ch * 4, 128>>>(ch);

        // ctx[b][n][d] : M=196, N=ch, K=3840 ; z = b  (head-mean via alpha)
        gemm_p<MODE_CTX><<<dim3(gn, 2, 16), 256, SMEM_BYTES>>>(196, ch, 3840, 3840, 3840, ch, 0.25f, 0, 0, nullptr);
        // out[b][n][e] : M=196, N=ch, K=ch ; z = b
        gemm_p<MODE_OUT><<<dim3(gn, 2, 16), 256, SMEM_BYTES>>>(196, ch, ch, ch, ch, ch, 1.0f, 0, woff[i], out + ooff);
        ooff += (size_t)16 * 196 * ch;
    }
}

// round 10
// speedup vs baseline: 2.6627x; 1.0374x over previous
#include <cuda_runtime.h>
#include <cuda_bf16.h>
#include <cstdint>
#include <math.h>

// B=16, N=196, KV=960, H=4, chs={64,128,256,512}

#define BM 128
#define BN 64
#define BK 32
#define STAGES 2
#define SAP 40                    // A smem row stride (u32), padded
#define SBP 40
#define A_STAGE (BM*SAP)          // 5120 u32
#define B_STAGE (BN*SBP)          // 2560 u32
#define B_POOL  (STAGES*A_STAGE)
#define SMEM_BYTES ((STAGES*(A_STAGE+B_STAGE))*4)   // 61440

#define MODE_K   0
#define MODE_V   1
#define MODE_Q   2
#define MODE_S   3
#define MODE_CTX 4
#define MODE_OUT 5

// ---------------- packed split-bf16 scratch (u32 = lo<<16 | hi) ----------------
__device__ unsigned g_embap[3136*960];              // emb_all packed [3136][960]
__device__ unsigned g_Wkp  [4*960*960];             // [h][j][k]
__device__ unsigned g_Wvp  [4*960*960];
__device__ unsigned g_embp [3136*960];              // 4 embs concatenated
__device__ unsigned g_Wqp  [1392640];               // 4 scales of [h][d][c]
__device__ unsigned g_Wop  [348160];                // 4 scales of [e][d]
__device__ unsigned g_Ktp  [(size_t)4*16*960*196];  // [h*16+b][j][n]
__device__ unsigned g_Vp   [(size_t)16*196*3840];   // [b][n][h*960+j]
__device__ unsigned g_Qp   [12042240];              // ALL scales [s][b*4+h][d][n]
__device__ float    g_S    [58982400];              // ALL scales fp32 scores
__device__ unsigned g_Pp   [58982400];              // probs packed, same layout
__device__ unsigned g_ctxp [3010560];               // ALL scales [s][b][n][d]
__device__ float    g_part [8192];                  // 4096 partials x (sum,sumsq)

// per-scale offset tables (compile-time)
#define SOFF(s)  ((s)==0?0:((s)==1?3932160:((s)==2?11796480:27525120)))
#define QPOFF(s) ((s)==0?0:((s)==1?802816:((s)==2?2408448:5619712)))
#define COFF(s)  ((s)==0?0:((s)==1?200704:((s)==2?602112:1404928)))
#define QWOFF(s) ((s)==0?0:((s)==1?16384:((s)==2?81920:344064)))
#define WOFF(s)  ((s)==0?0:((s)==1?4096:((s)==2?20480:86016)))

// ---------------- helpers ----------------
__device__ __forceinline__ unsigned pack2(float v) {
    unsigned short h = __bfloat16_as_ushort(__float2bfloat16_rn(v));
    float hf = __bfloat162float(__ushort_as_bfloat16(h));
    unsigned short l = __bfloat16_as_ushort(__float2bfloat16_rn(v - hf));
    return (unsigned)h | ((unsigned)l << 16);
}

#define MMA_OP(d, a, b) asm volatile( \
    "mma.sync.aligned.m16n8k16.row.col.f32.bf16.bf16.f32 " \
    "{%0,%1,%2,%3},{%4,%5,%6,%7},{%8,%9},{%0,%1,%2,%3};" \
    : "+f"(d[0]), "+f"(d[1]), "+f"(d[2]), "+f"(d[3]) \
    : "r"(a[0]), "r"(a[1]), "r"(a[2]), "r"(a[3]), "r"(b[0]), "r"(b[1]))

__device__ __forceinline__ void cp16(unsigned* sdst, const unsigned* g) {
    unsigned sa = (unsigned)__cvta_generic_to_shared(sdst);
    asm volatile("cp.async.cg.shared.global [%0],[%1],16;\n" :: "r"(sa), "l"(g) : "memory");
}
__device__ __forceinline__ void cp_commit() {
    asm volatile("cp.async.commit_group;\n" ::: "memory");
}

// ---------------- tile loader (gmem packed -> smem, zero-filled) ----------------
__device__ __forceinline__ void load_stage(unsigned* su, int stage,
    const unsigned* __restrict__ A, const unsigned* __restrict__ B,
    int m0, int n0, int k0, int M, int N, int K, int lda, int ldb, int tid)
{
    const int q = tid & 7, r0 = tid >> 3;
#pragma unroll
    for (int it = 0; it < 4; it++) {
        int row = r0 + it * 32;
        int gm = m0 + row;
        unsigned* sdst = su + stage * A_STAGE + row * SAP + q * 4;
        int k = k0 + q * 4;
        if (gm < M && k + 3 < K) {
            cp16(sdst, A + (size_t)gm * lda + k);
        } else {
            uint4 v = make_uint4(0, 0, 0, 0);
            if (gm < M) {
                const unsigned* src = A + (size_t)gm * lda;
                if (k + 0 < K) v.x = src[k + 0];
                if (k + 1 < K) v.y = src[k + 1];
                if (k + 2 < K) v.z = src[k + 2];
                if (k + 3 < K) v.w = src[k + 3];
            }
            *(uint4*)sdst = v;
        }
    }
#pragma unroll
    for (int it = 0; it < 2; it++) {
        int row = r0 + it * 32;
        int gn = n0 + row;
        unsigned* sdst = su + B_POOL + stage * B_STAGE + row * SBP + q * 4;
        int k = k0 + q * 4;
        if (gn < N && k + 3 < K) {
            cp16(sdst, B + (size_t)gn * ldb + k);
        } else {
            uint4 v = make_uint4(0, 0, 0, 0);
            if (gn < N) {
                const unsigned* src = B + (size_t)gn * ldb;
                if (k + 0 < K) v.x = src[k + 0];
                if (k + 1 < K) v.y = src[k + 1];
                if (k + 2 < K) v.z = src[k + 2];
                if (k + 3 < K) v.w = src[k + 3];
            }
            *(uint4*)sdst = v;
        }
    }
}

// ---------------- per-stage MMA compute (R2/R8-proven) ----------------
__device__ __forceinline__ void compute_stage(const unsigned* su, int stage,
    float (&acc)[2][4][4], int wm, int wn, int g, int q2)
{
    const unsigned* sa = su + stage * A_STAGE;
    const unsigned* sb = su + B_POOL + stage * B_STAGE;
#pragma unroll
    for (int kk = 0; kk < BK; kk += 16) {
        unsigned ah[2][4], al[2][4], bh[4][2], bl[4][2];
#pragma unroll
        for (int i = 0; i < 2; i++) {
            int r = wm + i * 16 + g;
            uint2 w0 = *(const uint2*)(sa + r * SAP + kk + q2);
            uint2 w1 = *(const uint2*)(sa + (r + 8) * SAP + kk + q2);
            uint2 w2 = *(const uint2*)(sa + r * SAP + kk + 8 + q2);
            uint2 w3 = *(const uint2*)(sa + (r + 8) * SAP + kk + 8 + q2);
            ah[i][0] = __byte_perm(w0.x, w0.y, 0x5410); al[i][0] = __byte_perm(w0.x, w0.y, 0x7632);
            ah[i][1] = __byte_perm(w1.x, w1.y, 0x5410); al[i][1] = __byte_perm(w1.x, w1.y, 0x7632);
            ah[i][2] = __byte_perm(w2.x, w2.y, 0x5410); al[i][2] = __byte_perm(w2.x, w2.y, 0x7632);
            ah[i][3] = __byte_perm(w3.x, w3.y, 0x5410); al[i][3] = __byte_perm(w3.x, w3.y, 0x7632);
        }
#pragma unroll
        for (int j = 0; j < 4; j++) {
            int c = wn + j * 8 + g;
            uint2 u0 = *(const uint2*)(sb + c * SBP + kk + q2);
            uint2 u1 = *(const uint2*)(sb + c * SBP + kk + 8 + q2);
            bh[j][0] = __byte_perm(u0.x, u0.y, 0x5410); bl[j][0] = __byte_perm(u0.x, u0.y, 0x7632);
            bh[j][1] = __byte_perm(u1.x, u1.y, 0x5410); bl[j][1] = __byte_perm(u1.x, u1.y, 0x7632);
        }
#pragma unroll
        for (int i = 0; i < 2; i++)
#pragma unroll
            for (int j = 0; j < 4; j++) {
                MMA_OP(acc[i][j], ah[i], bh[j]);
                MMA_OP(acc[i][j], ah[i], bl[j]);
                MMA_OP(acc[i][j], al[i], bh[j]);
            }
    }
}

// ---------------- GEMM: C = alpha * A[M][K] * B[N][K]^T, multi-scale decode ----
template <int MODE>
__global__ __launch_bounds__(256, 2)
void gemm_p(float* Cg)
{
    extern __shared__ unsigned su[];
    const int z = blockIdx.z;

    // ---- decode (scale s, tile x/y) ----
    int s = 0, x, y;
    if (MODE == MODE_K || MODE == MODE_V) {
        x = blockIdx.x; y = blockIdx.y;
    } else if (MODE == MODE_Q) {
        int bx = blockIdx.x;                      // prefix {0,4,8,16}, counts 4*cy
        s = (bx < 4) ? 0 : (bx < 8) ? 1 : (bx < 16) ? 2 : 3;
        const int pref[4] = {0, 4, 8, 16};
        int loc = bx - pref[s];
        x = loc & 3; y = loc >> 2;
    } else if (MODE == MODE_S) {
        int bx = blockIdx.x;                      // prefix {0,15,30,60}, counts 15*cy
        s = (bx < 15) ? 0 : (bx < 30) ? 1 : (bx < 60) ? 2 : 3;
        const int pref[4] = {0, 15, 30, 60};
        int loc = bx - pref[s];
        x = loc % 15; y = loc / 15;
    } else {                                      // CTX/OUT: prefix {0,2,6,14}, counts cx*2
        int bx = blockIdx.x;
        s = (bx < 2) ? 0 : (bx < 6) ? 1 : (bx < 14) ? 2 : 3;
        const int pref[4] = {0, 2, 6, 14};
        int loc = bx - pref[s];
        x = loc & ((1 << s) - 1); y = loc >> s;
    }
    const int ch = 64 << s;

    // ---- operands / dims ----
    const unsigned *A, *B;
    int M, N, K, lda, ldb;
    float alpha = 1.0f;
    if (MODE == MODE_K) {
        A = g_Wkp + (size_t)(z >> 4) * 921600;
        B = g_embap + (size_t)(z & 15) * 188160;
        M = 960; N = 196; K = 960; lda = 960; ldb = 960;
    } else if (MODE == MODE_V) {
        A = g_embap;
        B = g_Wvp + (size_t)z * 921600;
        M = 3136; N = 960; K = 960; lda = 960; ldb = 960;
    } else if (MODE == MODE_Q) {
        A = g_Wqp + QWOFF(s) + (size_t)(z & 3) * ch * ch;
        B = g_embp + COFF(s) + (size_t)(z >> 2) * 196 * ch;
        M = ch; N = 196; K = ch; lda = ch; ldb = ch;
    } else if (MODE == MODE_S) {
        A = g_Qp + QPOFF(s) + (size_t)z * ch * 196;
        B = g_Ktp + (size_t)((z & 3) * 16 + (z >> 2)) * 188160;
        M = ch; N = 960; K = 196; lda = 196; ldb = 196;
        alpha = 0.032274861218395144f;            // 1/sqrt(960)
    } else if (MODE == MODE_CTX) {
        A = g_Vp + (size_t)z * 752640;
        B = g_Pp + SOFF(s) + (size_t)z * ch * 3840;
        M = 196; N = ch; K = 3840; lda = 3840; ldb = 3840;
        alpha = 0.25f;                            // head mean
    } else {
        A = g_ctxp + COFF(s) + (size_t)z * 196 * ch;
        B = g_Wop + WOFF(s);
        M = 196; N = ch; K = ch; lda = ch; ldb = ch;
    }

    // ---- output base ----
    unsigned* outU = nullptr; float* outF = nullptr; int rs = 0;
    if (MODE == MODE_K)        { outU = g_Ktp + (size_t)z * 188160;                    rs = 196; }
    else if (MODE == MODE_V)   { outU = g_Vp + (size_t)z * 960;                        rs = 3840; }
    else if (MODE == MODE_Q)   { outU = g_Qp + QPOFF(s) + (size_t)z * ch * 196;        rs = 196; }
    else if (MODE == MODE_S)   { outF = g_S + SOFF(s) + (size_t)(z >> 2) * ch * 3840 + (z & 3) * 960; rs = 3840; }
    else if (MODE == MODE_CTX) { outU = g_ctxp + COFF(s) + (size_t)z * 196 * ch;       rs = ch; }
    else                       { outF = Cg + COFF(s) + (size_t)z * 196 * ch;           rs = ch; }

    const int m0 = y * BM, n0 = x * BN;
    const int tid = threadIdx.x;
    const int warp = tid >> 5, lane = tid & 31;
    const int wm = (warp >> 1) * 32, wn = (warp & 1) * 32;
    const int g = lane >> 2, q2 = (lane & 3) * 2;

    float acc[2][4][4];
#pragma unroll
    for (int i = 0; i < 2; i++)
#pragma unroll
        for (int j = 0; j < 4; j++)
#pragma unroll
            for (int r = 0; r < 4; r++) acc[i][j][r] = 0.0f;

    const int nch = (K + BK - 1) / BK;
    const int pre = (STAGES - 1 < nch) ? STAGES - 1 : nch;
    for (int st = 0; st < pre; st++) {
        load_stage(su, st, A, B, m0, n0, st * BK, M, N, K, lda, ldb, tid);
        cp_commit();
    }
    for (int c = 0; c < nch; c++) {
        if (c + STAGES - 1 < nch) {
            load_stage(su, (c + STAGES - 1) % STAGES, A, B, m0, n0,
                       (c + STAGES - 1) * BK, M, N, K, lda, ldb, tid);
            cp_commit();
        }
        int issued = (c + STAGES < nch) ? c + STAGES : nch;
        int pend = issued - 1 - c;
        if (pend >= 1) asm volatile("cp.async.wait_group 1;\n" ::: "memory");
        else           asm volatile("cp.async.wait_group 0;\n" ::: "memory");
        __syncthreads();
        compute_stage(su, c % STAGES, acc, wm, wn, g, q2);
        __syncthreads();
    }

    // ---- epilogue ----
#pragma unroll
    for (int i = 0; i < 2; i++) {
#pragma unroll
        for (int rr = 0; rr < 2; rr++) {
            int m = m0 + wm + i * 16 + g + rr * 8;
            if (m >= M) continue;
#pragma unroll
            for (int j = 0; j < 4; j++) {
                int n = n0 + wn + j * 8 + q2;
                if (n >= N) continue;
                float v0 = acc[i][j][rr * 2]     * alpha;
                float v1 = acc[i][j][rr * 2 + 1] * alpha;
                if (MODE == MODE_S || MODE == MODE_OUT) {
                    *(float2*)(outF + (size_t)m * rs + n) = make_float2(v0, v1);
                } else {
                    *(uint2*)(outU + (size_t)m * rs + n) = make_uint2(pack2(v0), pack2(v1));
                }
            }
        }
    }
}

// ---------------- fused fp32 -> packed split-bf16 (all 15 tensors) ----------------
struct PackArgs { const float* p[15]; };

__global__ void pack_all(PackArgs pa)
{
    const int nblk[15] = {11760,14400,14400,784,1568,3136,6272,64,256,1024,4096,16,64,256,1024};
    const int nsz [15] = {3010560,3686400,3686400,200704,401408,802816,1605632,
                          16384,65536,262144,1048576,4096,16384,65536,262144};
    int rem = blockIdx.x, seg = 0;
    while (rem >= nblk[seg]) { rem -= nblk[seg]; seg++; }
    int i = rem * 256 + threadIdx.x;
    if (i >= nsz[seg]) return;
    unsigned v = pack2(pa.p[seg][i]);
    switch (seg) {
        case 0:  g_embap[i] = v; break;
        case 1:  g_Wkp[i] = v; break;
        case 2:  g_Wvp[i] = v; break;
        case 3:  g_embp[i] = v; break;
        case 4:  g_embp[200704 + i] = v; break;
        case 5:  g_embp[602112 + i] = v; break;
        case 6:  g_embp[1404928 + i] = v; break;
        case 7:  g_Wqp[i] = v; break;
        case 8:  g_Wqp[16384 + i] = v; break;
        case 9:  g_Wqp[81920 + i] = v; break;
        case 10: g_Wqp[344064 + i] = v; break;
        case 11: g_Wop[i] = v; break;
        case 12: g_Wop[4096 + i] = v; break;
        case 13: g_Wop[20480 + i] = v; break;
        default: g_Wop[86016 + i] = v; break;
    }
}

// ---------------- InstanceNorm stats, level-1 partials (16 slices per (s,z)) ----
__global__ __launch_bounds__(256)
void reduce_stats_p()
{
    const int bid = blockIdx.x;           // 4096 = s(4) * z(64) * slice(16)
    const int s = bid >> 10;
    const int rz = bid & 1023;
    const int z = rz >> 4, slice = rz & 15;
    const int ch = 64 << s;
    const int b = z >> 2, h = z & 3;
    const float* base = g_S + SOFF(s) + (size_t)b * ch * 3840 + h * 960;
    const int chunk = (ch * 960) >> 4;    // multiple of 256

    float sum = 0.f, ss = 0.f;
    const int end = (slice + 1) * chunk;
    for (int idx = slice * chunk + threadIdx.x; idx < end; idx += 256) {
        int d = idx / 960;
        int j = idx - d * 960;
        float v = base[(size_t)d * 3840 + j];
        sum += v; ss += v * v;
    }
    __shared__ float sh[256], sh2[256];
    sh[threadIdx.x] = sum; sh2[threadIdx.x] = ss;
    __syncthreads();
    for (int o = 128; o > 0; o >>= 1) {
        if (threadIdx.x < o) {
            sh[threadIdx.x]  += sh[threadIdx.x + o];
            sh2[threadIdx.x] += sh2[threadIdx.x + o];
        }
        __syncthreads();
    }
    if (threadIdx.x == 0) { g_part[bid * 2] = sh[0]; g_part[bid * 2 + 1] = sh2[0]; }
}

// ---------------- instance-norm + softmax (all scales) -> packed probs ----------
__global__ __launch_bounds__(128)
void softmax_all()
{
    int r = blockIdx.x;                   // prefix {0,4096,12288,28672}, counts 16*ch*4
    int s = (r < 4096) ? 0 : (r < 12288) ? 1 : (r < 28672) ? 2 : 3;
    const int pref[4] = {0, 4096, 12288, 28672};
    int loc = r - pref[s];
    const int ch = 64 << s;
    const int h = loc & 3;
    const int t2 = loc >> 2;
    const int d = t2 % ch;
    const int b = t2 / ch;

    const size_t off = (size_t)SOFF(s) + (size_t)b * ch * 3840 + (size_t)d * 3840 + (size_t)h * 960;
    const float* p = g_S + off;
    unsigned* po = g_Pp + off;

    // combine 16 partials (fixed order => identical across blocks)
    const int zz = b * 4 + h;
    float sum = 0.f, sumsq = 0.f;
#pragma unroll
    for (int sl = 0; sl < 16; sl++) {
        int pi = ((s * 64 + zz) * 16 + sl) * 2;
        sum += g_part[pi]; sumsq += g_part[pi + 1];
    }
    const float cnt = (float)ch * 960.0f;
    const float mean = sum / cnt;
    const float var = sumsq / cnt - mean * mean;
    const float inv = rsqrtf(var + 1e-5f);

    const int t = threadIdx.x;
    float v[8];
    float mx = -1e30f;
#pragma unroll
    for (int k = 0; k < 8; k++) {
        int j = t + k * 128;
        v[k] = (j < 960) ? (p[j] - mean) * inv : -1e30f;
        mx = fmaxf(mx, v[k]);
    }
    __shared__ float sh[128];
    sh[t] = mx; __syncthreads();
    for (int o = 64; o > 0; o >>= 1) {
        if (t < o) sh[t] = fmaxf(sh[t], sh[t + o]);
        __syncthreads();
    }
    mx = sh[0]; __syncthreads();

    float lsum = 0.f;
#pragma unroll
    for (int k = 0; k < 8; k++) {
        int j = t + k * 128;
        if (j < 960) { v[k] = __expf(v[k] - mx); lsum += v[k]; }
    }
    sh[t] = lsum; __syncthreads();
    for (int o = 64; o > 0; o >>= 1) {
        if (t < o) sh[t] += sh[t + o];
        __syncthreads();
    }
    const float rden = 1.0f / sh[0];
#pragma unroll
    for (int k = 0; k < 8; k++) {
        int j = t + k * 128;
        if (j < 960) po[j] = pack2(v[k] * rden);
    }
}

// ---------------- launch ----------------
extern "C" void kernel_launch(void* const* d_in, const int* in_sizes, int n_in,
                              void* d_out, int out_size)
{
    float* out = (float*)d_out;

    cudaFuncSetAttribute((const void*)gemm_p<MODE_K>,   cudaFuncAttributeMaxDynamicSharedMemorySize, SMEM_BYTES);
    cudaFuncSetAttribute((const void*)gemm_p<MODE_V>,   cudaFuncAttributeMaxDynamicSharedMemorySize, SMEM_BYTES);
    cudaFuncSetAttribute((const void*)gemm_p<MODE_Q>,   cudaFuncAttributeMaxDynamicSharedMemorySize, SMEM_BYTES);
    cudaFuncSetAttribute((const void*)gemm_p<MODE_S>,   cudaFuncAttributeMaxDynamicSharedMemorySize, SMEM_BYTES);
    cudaFuncSetAttribute((const void*)gemm_p<MODE_CTX>, cudaFuncAttributeMaxDynamicSharedMemorySize, SMEM_BYTES);
    cudaFuncSetAttribute((const void*)gemm_p<MODE_OUT>, cudaFuncAttributeMaxDynamicSharedMemorySize, SMEM_BYTES);

    // fused input packing: emb_all, Wk, Wv, emb0-3, Wq0-3, Wo0-3
    PackArgs pa;
    pa.p[0] = (const float*)d_in[4];   // emb_all
    pa.p[1] = (const float*)d_in[13];  // Wk
    pa.p[2] = (const float*)d_in[14];  // Wv
    pa.p[3] = (const float*)d_in[0];   // emb0
    pa.p[4] = (const float*)d_in[1];
    pa.p[5] = (const float*)d_in[2];
    pa.p[6] = (const float*)d_in[3];
    pa.p[7] = (const float*)d_in[5];   // Wq0
    pa.p[8] = (const float*)d_in[7];
    pa.p[9] = (const float*)d_in[9];
    pa.p[10] = (const float*)d_in[11];
    pa.p[11] = (const float*)d_in[6];  // Wo0
    pa.p[12] = (const float*)d_in[8];
    pa.p[13] = (const float*)d_in[10];
    pa.p[14] = (const float*)d_in[12];
    pack_all<<<59120, 256>>>(pa);

    // K^T and V projections (shared by all scales)
    gemm_p<MODE_K><<<dim3(4, 8, 64), 256, SMEM_BYTES>>>(nullptr);
    gemm_p<MODE_V><<<dim3(15, 25, 4), 256, SMEM_BYTES>>>(nullptr);

    // all scales, phase-merged
    gemm_p<MODE_Q>  <<<dim3(32, 1, 64),  256, SMEM_BYTES>>>(nullptr);
    gemm_p<MODE_S>  <<<dim3(120, 1, 64), 256, SMEM_BYTES>>>(nullptr);
    reduce_stats_p  <<<4096, 256>>>();
    softmax_all     <<<61440, 128>>>();
    gemm_p<MODE_CTX><<<dim3(30, 1, 16),  256, SMEM_BYTES>>>(nullptr);
    gemm_p<MODE_OUT><<<dim3(30, 1, 16),  256, SMEM_BYTES>>>(out);
}

// round 11
// speedup vs baseline: 3.3483x; 1.2575x over previous
#include <cuda_runtime.h>
#include <cuda_bf16.h>
#include <cstdint>
#include <math.h>

// B=16, N=196, KV=960, H=4, chs={64,128,256,512}

#define BM 128
#define BN 64
#define BK 32
#define STAGES 2
#define SAP 40                    // A smem row stride (u32), padded
#define SBP 40
#define A_STAGE (BM*SAP)          // 5120 u32
#define B_STAGE (BN*SBP)          // 2560 u32
#define B_POOL  (STAGES*A_STAGE)
#define SMEM_BYTES ((STAGES*(A_STAGE+B_STAGE))*4)   // 61440

#define MODE_VKQ 0
#define MODE_S   1
#define MODE_CTX 2
#define MODE_OUT 3

// ---------------- packed split-bf16 scratch (u32 = lo<<16 | hi) ----------------
__device__ unsigned g_embap[3136*960];              // emb_all packed [3136][960]
__device__ unsigned g_Wkp  [4*960*960];             // [h][j][k]
__device__ unsigned g_Wvp  [4*960*960];
__device__ unsigned g_embp [3136*960];              // 4 embs concatenated
__device__ unsigned g_Wqp  [1392640];               // 4 scales of [h][d][c]
__device__ unsigned g_Wop  [348160];                // 4 scales of [e][d]
__device__ unsigned g_Ktp  [(size_t)4*16*960*196];  // [h*16+b][j][n]
__device__ unsigned g_Vp   [(size_t)16*196*3840];   // [b][n][h*960+j]
__device__ unsigned g_Qp   [12042240];              // ALL scales [s][b*4+h][d][n]
__device__ float    g_S    [58982400];              // ALL scales fp32 scores
__device__ unsigned g_Pp   [58982400];              // probs packed, same layout
__device__ float    g_ctxh [12042240];              // 4 head-partials x all-scale ctx (fp32)
__device__ unsigned g_ctxp [3010560];               // ALL scales [s][b][n][d] packed
__device__ float    g_part [15360];                 // 7680 tiles x (sum,sumsq)

// per-scale offset tables (compile-time)
#define SOFF(s)  ((s)==0?0:((s)==1?3932160:((s)==2?11796480:27525120)))
#define QPOFF(s) ((s)==0?0:((s)==1?802816:((s)==2?2408448:5619712)))
#define COFF(s)  ((s)==0?0:((s)==1?200704:((s)==2?602112:1404928)))
#define QWOFF(s) ((s)==0?0:((s)==1?16384:((s)==2?81920:344064)))
#define WOFF(s)  ((s)==0?0:((s)==1?4096:((s)==2?20480:86016)))

// ---------------- helpers ----------------
__device__ __forceinline__ unsigned pack2(float v) {
    unsigned short h = __bfloat16_as_ushort(__float2bfloat16_rn(v));
    float hf = __bfloat162float(__ushort_as_bfloat16(h));
    unsigned short l = __bfloat16_as_ushort(__float2bfloat16_rn(v - hf));
    return (unsigned)h | ((unsigned)l << 16);
}

#define MMA_OP(d, a, b) asm volatile( \
    "mma.sync.aligned.m16n8k16.row.col.f32.bf16.bf16.f32 " \
    "{%0,%1,%2,%3},{%4,%5,%6,%7},{%8,%9},{%0,%1,%2,%3};" \
    : "+f"(d[0]), "+f"(d[1]), "+f"(d[2]), "+f"(d[3]) \
    : "r"(a[0]), "r"(a[1]), "r"(a[2]), "r"(a[3]), "r"(b[0]), "r"(b[1]))

__device__ __forceinline__ void cp16(unsigned* sdst, const unsigned* g) {
    unsigned sa = (unsigned)__cvta_generic_to_shared(sdst);
    asm volatile("cp.async.cg.shared.global [%0],[%1],16;\n" :: "r"(sa), "l"(g) : "memory");
}
__device__ __forceinline__ void cp_commit() {
    asm volatile("cp.async.commit_group;\n" ::: "memory");
}

// ---------------- tile loader (gmem packed -> smem, zero-filled) ----------------
__device__ __forceinline__ void load_stage(unsigned* su, int stage,
    const unsigned* __restrict__ A, const unsigned* __restrict__ B,
    int m0, int n0, int k0, int M, int N, int K, int lda, int ldb, int tid)
{
    const int q = tid & 7, r0 = tid >> 3;
#pragma unroll
    for (int it = 0; it < 4; it++) {
        int row = r0 + it * 32;
        int gm = m0 + row;
        unsigned* sdst = su + stage * A_STAGE + row * SAP + q * 4;
        int k = k0 + q * 4;
        if (gm < M && k + 3 < K) {
            cp16(sdst, A + (size_t)gm * lda + k);
        } else {
            uint4 v = make_uint4(0, 0, 0, 0);
            if (gm < M) {
                const unsigned* src = A + (size_t)gm * lda;
                if (k + 0 < K) v.x = src[k + 0];
                if (k + 1 < K) v.y = src[k + 1];
                if (k + 2 < K) v.z = src[k + 2];
                if (k + 3 < K) v.w = src[k + 3];
            }
            *(uint4*)sdst = v;
        }
    }
#pragma unroll
    for (int it = 0; it < 2; it++) {
        int row = r0 + it * 32;
        int gn = n0 + row;
        unsigned* sdst = su + B_POOL + stage * B_STAGE + row * SBP + q * 4;
        int k = k0 + q * 4;
        if (gn < N && k + 3 < K) {
            cp16(sdst, B + (size_t)gn * ldb + k);
        } else {
            uint4 v = make_uint4(0, 0, 0, 0);
            if (gn < N) {
                const unsigned* src = B + (size_t)gn * ldb;
                if (k + 0 < K) v.x = src[k + 0];
                if (k + 1 < K) v.y = src[k + 1];
                if (k + 2 < K) v.z = src[k + 2];
                if (k + 3 < K) v.w = src[k + 3];
            }
            *(uint4*)sdst = v;
        }
    }
}

// ---------------- per-stage MMA compute (R2/R8/R10-proven) ----------------
__device__ __forceinline__ void compute_stage(const unsigned* su, int stage,
    float (&acc)[2][4][4], int wm, int wn, int g, int q2)
{
    const unsigned* sa = su + stage * A_STAGE;
    const unsigned* sb = su + B_POOL + stage * B_STAGE;
#pragma unroll
    for (int kk = 0; kk < BK; kk += 16) {
        unsigned ah[2][4], al[2][4], bh[4][2], bl[4][2];
#pragma unroll
        for (int i = 0; i < 2; i++) {
            int r = wm + i * 16 + g;
            uint2 w0 = *(const uint2*)(sa + r * SAP + kk + q2);
            uint2 w1 = *(const uint2*)(sa + (r + 8) * SAP + kk + q2);
            uint2 w2 = *(const uint2*)(sa + r * SAP + kk + 8 + q2);
            uint2 w3 = *(const uint2*)(sa + (r + 8) * SAP + kk + 8 + q2);
            ah[i][0] = __byte_perm(w0.x, w0.y, 0x5410); al[i][0] = __byte_perm(w0.x, w0.y, 0x7632);
            ah[i][1] = __byte_perm(w1.x, w1.y, 0x5410); al[i][1] = __byte_perm(w1.x, w1.y, 0x7632);
            ah[i][2] = __byte_perm(w2.x, w2.y, 0x5410); al[i][2] = __byte_perm(w2.x, w2.y, 0x7632);
            ah[i][3] = __byte_perm(w3.x, w3.y, 0x5410); al[i][3] = __byte_perm(w3.x, w3.y, 0x7632);
        }
#pragma unroll
        for (int j = 0; j < 4; j++) {
            int c = wn + j * 8 + g;
            uint2 u0 = *(const uint2*)(sb + c * SBP + kk + q2);
            uint2 u1 = *(const uint2*)(sb + c * SBP + kk + 8 + q2);
            bh[j][0] = __byte_perm(u0.x, u0.y, 0x5410); bl[j][0] = __byte_perm(u0.x, u0.y, 0x7632);
            bh[j][1] = __byte_perm(u1.x, u1.y, 0x5410); bl[j][1] = __byte_perm(u1.x, u1.y, 0x7632);
        }
#pragma unroll
        for (int i = 0; i < 2; i++)
#pragma unroll
            for (int j = 0; j < 4; j++) {
                MMA_OP(acc[i][j], ah[i], bh[j]);
                MMA_OP(acc[i][j], ah[i], bl[j]);
                MMA_OP(acc[i][j], al[i], bh[j]);
            }
    }
}

// ---------------- GEMM: C = alpha * A[M][K] * B[N][K]^T ----------------
template <int MODE>
__global__ __launch_bounds__(256, 2)
void gemm_p(float* Cg)
{
    extern __shared__ unsigned su[];

    const unsigned *A, *B;
    int M, N, K, lda, ldb;
    float alpha = 1.0f;
    unsigned* outU = nullptr;
    float* outF = nullptr;
    int rs = 0, m0, n0, spart = 0;

    if (MODE == MODE_VKQ) {
        int bx = blockIdx.x;
        if (bx < 1500) {            // V: x(15) y(25) z(4 heads)
            int x = bx % 15; int t = bx / 15; int y = t % 25; int z = t / 25;
            A = g_embap; B = g_Wvp + (size_t)z * 921600;
            M = 3136; N = 960; K = 960; lda = 960; ldb = 960;
            outU = g_Vp + (size_t)z * 960; rs = 3840;
            m0 = y * BM; n0 = x * BN;
        } else if (bx < 3548) {     // K: x(4) y(8) z(64 = h*16+b)
            int l = bx - 1500; int x = l & 3; int y = (l >> 2) & 7; int z = l >> 5;
            A = g_Wkp + (size_t)(z >> 4) * 921600;
            B = g_embap + (size_t)(z & 15) * 188160;
            M = 960; N = 196; K = 960; lda = 960; ldb = 960;
            outU = g_Ktp + (size_t)z * 188160; rs = 196;
            m0 = y * BM; n0 = x * BN;
        } else {                    // Q: z(64 = b*4+h), rem(32) -> scale/x/y
            int l = bx - 3548; int z = l >> 5; int rem = l & 31;
            int s = (rem < 4) ? 0 : (rem < 8) ? 1 : (rem < 16) ? 2 : 3;
            const int pref[4] = {0, 4, 8, 16};
            int loc = rem - pref[s];
            int x = loc & 3, y = loc >> 2;
            int ch = 64 << s;
            A = g_Wqp + QWOFF(s) + (size_t)(z & 3) * ch * ch;
            B = g_embp + COFF(s) + (size_t)(z >> 2) * 196 * ch;
            M = ch; N = 196; K = ch; lda = ch; ldb = ch;
            outU = g_Qp + QPOFF(s) + (size_t)z * ch * 196; rs = 196;
            m0 = y * BM; n0 = x * BN;
        }
    } else if (MODE == MODE_S) {
        int z = blockIdx.z;
        int bx = blockIdx.x;
        int s = (bx < 15) ? 0 : (bx < 30) ? 1 : (bx < 60) ? 2 : 3;
        const int pref[4] = {0, 15, 30, 60};
        int loc = bx - pref[s];
        int x = loc % 15, y = loc / 15;
        int ch = 64 << s;
        A = g_Qp + QPOFF(s) + (size_t)z * ch * 196;
        B = g_Ktp + (size_t)((z & 3) * 16 + (z >> 2)) * 188160;
        M = ch; N = 960; K = 196; lda = 196; ldb = 196;
        alpha = 0.032274861218395144f;            // 1/sqrt(960)
        outF = g_S + SOFF(s) + (size_t)(z >> 2) * ch * 3840 + (z & 3) * 960; rs = 3840;
        const int PB[4] = {0, 960, 1920, 3840};
        const int T[4] = {15, 15, 30, 60};
        spart = PB[s] + z * T[s] + y * 15 + x;
        m0 = y * BM; n0 = x * BN;
    } else if (MODE == MODE_CTX) {               // split by head: z = b*4+h
        int z = blockIdx.z;
        int b = z >> 2, h = z & 3;
        int bx = blockIdx.x;
        int s = (bx < 2) ? 0 : (bx < 6) ? 1 : (bx < 14) ? 2 : 3;
        const int pref[4] = {0, 2, 6, 14};
        int loc = bx - pref[s];
        int x = loc & ((1 << s) - 1), y = loc >> s;
        int ch = 64 << s;
        A = g_Vp + (size_t)b * 752640 + h * 960;
        B = g_Pp + SOFF(s) + (size_t)b * ch * 3840 + h * 960;
        M = 196; N = ch; K = 960; lda = 3840; ldb = 3840;
        alpha = 0.25f;                            // head mean
        outF = g_ctxh + (size_t)h * 3010560 + COFF(s) + (size_t)b * 196 * ch; rs = ch;
        m0 = y * BM; n0 = x * BN;
    } else {                                      // OUT: z = b
        int z = blockIdx.z;
        int bx = blockIdx.x;
        int s = (bx < 2) ? 0 : (bx < 6) ? 1 : (bx < 14) ? 2 : 3;
        const int pref[4] = {0, 2, 6, 14};
        int loc = bx - pref[s];
        int x = loc & ((1 << s) - 1), y = loc >> s;
        int ch = 64 << s;
        A = g_ctxp + COFF(s) + (size_t)z * 196 * ch;
        B = g_Wop + WOFF(s);
        M = 196; N = ch; K = ch; lda = ch; ldb = ch;
        outF = Cg + COFF(s) + (size_t)z * 196 * ch; rs = ch;
        m0 = y * BM; n0 = x * BN;
    }

    const int tid = threadIdx.x;
    const int warp = tid >> 5, lane = tid & 31;
    const int wm = (warp >> 1) * 32, wn = (warp & 1) * 32;
    const int g = lane >> 2, q2 = (lane & 3) * 2;

    float acc[2][4][4];
#pragma unroll
    for (int i = 0; i < 2; i++)
#pragma unroll
        for (int j = 0; j < 4; j++)
#pragma unroll
            for (int r = 0; r < 4; r++) acc[i][j][r] = 0.0f;

    const int nch = (K + BK - 1) / BK;
    const int pre = (STAGES - 1 < nch) ? STAGES - 1 : nch;
    for (int st = 0; st < pre; st++) {
        load_stage(su, st, A, B, m0, n0, st * BK, M, N, K, lda, ldb, tid);
        cp_commit();
    }
    for (int c = 0; c < nch; c++) {
        if (c + STAGES - 1 < nch) {
            load_stage(su, (c + STAGES - 1) % STAGES, A, B, m0, n0,
                       (c + STAGES - 1) * BK, M, N, K, lda, ldb, tid);
            cp_commit();
        }
        int issued = (c + STAGES < nch) ? c + STAGES : nch;
        int pend = issued - 1 - c;
        if (pend >= 1) asm volatile("cp.async.wait_group 1;\n" ::: "memory");
        else           asm volatile("cp.async.wait_group 0;\n" ::: "memory");
        __syncthreads();
        compute_stage(su, c % STAGES, acc, wm, wn, g, q2);
        __syncthreads();
    }

    // ---- epilogue ----
    float sp = 0.f, ssp = 0.f;
#pragma unroll
    for (int i = 0; i < 2; i++) {
#pragma unroll
        for (int rr = 0; rr < 2; rr++) {
            int m = m0 + wm + i * 16 + g + rr * 8;
            if (m >= M) continue;
#pragma unroll
            for (int j = 0; j < 4; j++) {
                int n = n0 + wn + j * 8 + q2;
                if (n >= N) continue;
                float v0 = acc[i][j][rr * 2]     * alpha;
                float v1 = acc[i][j][rr * 2 + 1] * alpha;
                if (MODE == MODE_VKQ) {
                    *(uint2*)(outU + (size_t)m * rs + n) = make_uint2(pack2(v0), pack2(v1));
                } else {
                    *(float2*)(outF + (size_t)m * rs + n) = make_float2(v0, v1);
                    if (MODE == MODE_S) {
                        sp  += v0 + v1;
                        ssp += v0 * v0 + v1 * v1;
                    }
                }
            }
        }
    }

    if (MODE == MODE_S) {
#pragma unroll
        for (int o = 16; o; o >>= 1) {
            sp  += __shfl_xor_sync(0xFFFFFFFFu, sp,  o);
            ssp += __shfl_xor_sync(0xFFFFFFFFu, ssp, o);
        }
        float* rb = (float*)su;                   // smem free after last compute+sync
        if (lane == 0) { rb[warp * 2] = sp; rb[warp * 2 + 1] = ssp; }
        __syncthreads();
        if (tid == 0) {
            float a = 0.f, b2 = 0.f;
            for (int w = 0; w < 8; w++) { a += rb[2 * w]; b2 += rb[2 * w + 1]; }
            g_part[spart * 2] = a; g_part[spart * 2 + 1] = b2;
        }
    }
}

// ---------------- fused fp32 -> packed split-bf16 (all 15 tensors, x4 vec) -------
struct PackArgs { const float* p[15]; };

__global__ void pack_all(PackArgs pa)
{
    const int nblk[15] = {2940,3600,3600,196,392,784,1568,16,64,256,1024,4,16,64,256};
    int rem = blockIdx.x, seg = 0;
    while (rem >= nblk[seg]) { rem -= nblk[seg]; seg++; }
    int i = rem * 1024 + threadIdx.x * 4;
    float4 v = *(const float4*)(pa.p[seg] + i);
    uint4 o;
    o.x = pack2(v.x); o.y = pack2(v.y); o.z = pack2(v.z); o.w = pack2(v.w);
    unsigned* dst;
    switch (seg) {
        case 0:  dst = g_embap; break;
        case 1:  dst = g_Wkp; break;
        case 2:  dst = g_Wvp; break;
        case 3:  dst = g_embp; break;
        case 4:  dst = g_embp + 200704; break;
        case 5:  dst = g_embp + 602112; break;
        case 6:  dst = g_embp + 1404928; break;
        case 7:  dst = g_Wqp; break;
        case 8:  dst = g_Wqp + 16384; break;
        case 9:  dst = g_Wqp + 81920; break;
        case 10: dst = g_Wqp + 344064; break;
        case 11: dst = g_Wop; break;
        case 12: dst = g_Wop + 4096; break;
        case 13: dst = g_Wop + 20480; break;
        default: dst = g_Wop + 86016; break;
    }
    *(uint4*)(dst + i) = o;
}

// ---------------- instance-norm + softmax (all scales) -> packed probs ----------
__global__ __launch_bounds__(128)
void softmax_all()
{
    int r = blockIdx.x;                   // prefix {0,4096,12288,28672}
    int s = (r < 4096) ? 0 : (r < 12288) ? 1 : (r < 28672) ? 2 : 3;
    const int pref[4] = {0, 4096, 12288, 28672};
    int loc = r - pref[s];
    const int ch = 64 << s;
    const int h = loc & 3;
    const int t2 = loc >> 2;
    const int d = t2 % ch;
    const int b = t2 / ch;

    const size_t off = (size_t)SOFF(s) + (size_t)b * ch * 3840 + (size_t)d * 3840 + (size_t)h * 960;
    const float* p = g_S + off;
    unsigned* po = g_Pp + off;

    // combine per-tile partials (fixed order => identical across blocks)
    const int zz = b * 4 + h;
    const int Ts[4] = {15, 15, 30, 60};
    const int PBs[4] = {0, 960, 1920, 3840};
    float sum = 0.f, sumsq = 0.f;
    {
        int base = (PBs[s] + zz * Ts[s]) * 2;
        int T = Ts[s];
        for (int t = 0; t < T; t++) { sum += g_part[base + 2 * t]; sumsq += g_part[base + 2 * t + 1]; }
    }
    const float cnt = (float)ch * 960.0f;
    const float mean = sum / cnt;
    const float var = sumsq / cnt - mean * mean;
    const float inv = rsqrtf(var + 1e-5f);

    const int t = threadIdx.x;
    float v[8];
    float mx = -1e30f;
#pragma unroll
    for (int k = 0; k < 8; k++) {
        int j = t + k * 128;
        v[k] = (j < 960) ? (p[j] - mean) * inv : -1e30f;
        mx = fmaxf(mx, v[k]);
    }
    __shared__ float sh[128];
    sh[t] = mx; __syncthreads();
    for (int o = 64; o > 0; o >>= 1) {
        if (t < o) sh[t] = fmaxf(sh[t], sh[t + o]);
        __syncthreads();
    }
    mx = sh[0]; __syncthreads();

    float lsum = 0.f;
#pragma unroll
    for (int k = 0; k < 8; k++) {
        int j = t + k * 128;
        if (j < 960) { v[k] = __expf(v[k] - mx); lsum += v[k]; }
    }
    sh[t] = lsum; __syncthreads();
    for (int o = 64; o > 0; o >>= 1) {
        if (t < o) sh[t] += sh[t + o];
        __syncthreads();
    }
    const float rden = 1.0f / sh[0];
#pragma unroll
    for (int k = 0; k < 8; k++) {
        int j = t + k * 128;
        if (j < 960) po[j] = pack2(v[k] * rden);
    }
}

// ---------------- sum 4 head-partials -> packed ctx (fixed order) ----------------
__global__ void ctx_combine()
{
    int i = (blockIdx.x * 256 + threadIdx.x) * 4;
    if (i >= 3010560) return;
    float4 a = *(const float4*)(g_ctxh + i);
    float4 b = *(const float4*)(g_ctxh + 3010560 + i);
    float4 c = *(const float4*)(g_ctxh + 6021120 + i);
    float4 d = *(const float4*)(g_ctxh + 9031680 + i);
    uint4 o;
    o.x = pack2(((a.x + b.x) + c.x) + d.x);
    o.y = pack2(((a.y + b.y) + c.y) + d.y);
    o.z = pack2(((a.z + b.z) + c.z) + d.z);
    o.w = pack2(((a.w + b.w) + c.w) + d.w);
    *(uint4*)(g_ctxp + i) = o;
}

// ---------------- launch ----------------
extern "C" void kernel_launch(void* const* d_in, const int* in_sizes, int n_in,
                              void* d_out, int out_size)
{
    float* out = (float*)d_out;

    cudaFuncSetAttribute((const void*)gemm_p<MODE_VKQ>, cudaFuncAttributeMaxDynamicSharedMemorySize, SMEM_BYTES);
    cudaFuncSetAttribute((const void*)gemm_p<MODE_S>,   cudaFuncAttributeMaxDynamicSharedMemorySize, SMEM_BYTES);
    cudaFuncSetAttribute((const void*)gemm_p<MODE_CTX>, cudaFuncAttributeMaxDynamicSharedMemorySize, SMEM_BYTES);
    cudaFuncSetAttribute((const void*)gemm_p<MODE_OUT>, cudaFuncAttributeMaxDynamicSharedMemorySize, SMEM_BYTES);

    // fused input packing: emb_all, Wk, Wv, emb0-3, Wq0-3, Wo0-3
    PackArgs pa;
    pa.p[0] = (const float*)d_in[4];   // emb_all
    pa.p[1] = (const float*)d_in[13];  // Wk
    pa.p[2] = (const float*)d_in[14];  // Wv
    pa.p[3] = (const float*)d_in[0];   // emb0
    pa.p[4] = (const float*)d_in[1];
    pa.p[5] = (const float*)d_in[2];
    pa.p[6] = (const float*)d_in[3];
    pa.p[7] = (const float*)d_in[5];   // Wq0
    pa.p[8] = (const float*)d_in[7];
    pa.p[9] = (const float*)d_in[9];
    pa.p[10] = (const float*)d_in[11];
    pa.p[11] = (const float*)d_in[6];  // Wo0
    pa.p[12] = (const float*)d_in[8];
    pa.p[13] = (const float*)d_in[10];
    pa.p[14] = (const float*)d_in[12];
    pack_all<<<14780, 256>>>(pa);

    // V (1500 long blocks first) + K (2048) + Q (2048) merged
    gemm_p<MODE_VKQ><<<5596, 256, SMEM_BYTES>>>(nullptr);

    // scores (with fused instance-norm partial stats)
    gemm_p<MODE_S><<<dim3(120, 1, 64), 256, SMEM_BYTES>>>(nullptr);

    softmax_all<<<61440, 128>>>();

    // ctx, split per head (z = b*4+h), fp32 partials
    gemm_p<MODE_CTX><<<dim3(30, 1, 64), 256, SMEM_BYTES>>>(nullptr);
    ctx_combine<<<2940, 256>>>();

    // out projection
    gemm_p<MODE_OUT><<<dim3(30, 1, 16), 256, SMEM_BYTES>>>(out);
}

// round 12
// speedup vs baseline: 3.5969x; 1.0742x over previous
#include <cuda_runtime.h>
#include <cuda_bf16.h>
#include <cstdint>
#include <math.h>

// B=16, N=196, KV=960, H=4, chs={64,128,256,512}

#define BM 128
#define BN 64
#define BK 32
#define STAGES 2
#define SAP 40                    // A smem row stride (u32), padded
#define SBP 40
#define A_STAGE (BM*SAP)          // 5120 u32
#define B_STAGE (BN*SBP)          // 2560 u32
#define B_POOL  (STAGES*A_STAGE)
#define SMEM_BYTES ((STAGES*(A_STAGE+B_STAGE))*4)   // 61440

#define MODE_VKQ 0
#define MODE_S   1
#define MODE_CTX 2
#define MODE_OUT 3

// ---------------- packed split-bf16 scratch (u32 = lo<<16 | hi) ----------------
__device__ unsigned g_embap[3136*960];              // emb_all packed [3136][960]
__device__ unsigned g_Wkp  [4*960*960];             // [h][j][k]
__device__ unsigned g_Wvp  [4*960*960];
__device__ unsigned g_embp [3136*960];              // 4 embs concatenated
__device__ unsigned g_Wqp  [1392640];               // 4 scales of [h][d][c]
__device__ unsigned g_Wop  [348160];                // 4 scales of [e][d]
__device__ unsigned g_Ktp  [(size_t)4*16*960*196];  // [h*16+b][j][n]
__device__ unsigned g_Vp   [(size_t)16*196*3840];   // [b][n][h*960+j]
__device__ unsigned g_Qp   [12042240];              // ALL scales [s][b*4+h][d][n]
__device__ float    g_S    [58982400];              // ALL scales fp32 scores
__device__ unsigned g_Pp   [58982400];              // probs packed, same layout
__device__ float    g_ctxh [12042240];              // 4 head-partials x all-scale ctx (fp32)
__device__ unsigned g_ctxp [3010560];               // ALL scales [s][b][n][d] packed
__device__ float    g_part [15360];                 // 7680 tiles x (sum,sumsq)
__device__ float    g_stats[512];                   // per (s,z): mean, inv

// per-scale offset tables (compile-time)
#define SOFF(s)  ((s)==0?0:((s)==1?3932160:((s)==2?11796480:27525120)))
#define QPOFF(s) ((s)==0?0:((s)==1?802816:((s)==2?2408448:5619712)))
#define COFF(s)  ((s)==0?0:((s)==1?200704:((s)==2?602112:1404928)))
#define QWOFF(s) ((s)==0?0:((s)==1?16384:((s)==2?81920:344064)))
#define WOFF(s)  ((s)==0?0:((s)==1?4096:((s)==2?20480:86016)))

// ---------------- helpers ----------------
// pair pack: two fp32 -> two packed u32 (lo<<16 | hi), bf16 _rn rounding
__device__ __forceinline__ uint2 pack2x(float v0, float v1) {
    __nv_bfloat162 H = __floats2bfloat162_rn(v0, v1);
    unsigned Hu = *(unsigned*)&H;                     // [h1 | h0]
    float f0 = __uint_as_float(Hu << 16);
    float f1 = __uint_as_float(Hu & 0xffff0000u);
    __nv_bfloat162 L = __floats2bfloat162_rn(v0 - f0, v1 - f1);
    unsigned Lu = *(unsigned*)&L;
    return make_uint2(__byte_perm(Hu, Lu, 0x5410), __byte_perm(Hu, Lu, 0x7632));
}

#define MMA_OP(d, a, b) asm volatile( \
    "mma.sync.aligned.m16n8k16.row.col.f32.bf16.bf16.f32 " \
    "{%0,%1,%2,%3},{%4,%5,%6,%7},{%8,%9},{%0,%1,%2,%3};" \
    : "+f"(d[0]), "+f"(d[1]), "+f"(d[2]), "+f"(d[3]) \
    : "r"(a[0]), "r"(a[1]), "r"(a[2]), "r"(a[3]), "r"(b[0]), "r"(b[1]))

__device__ __forceinline__ void cp16(unsigned* sdst, const unsigned* g) {
    unsigned sa = (unsigned)__cvta_generic_to_shared(sdst);
    asm volatile("cp.async.cg.shared.global [%0],[%1],16;\n" :: "r"(sa), "l"(g) : "memory");
}
__device__ __forceinline__ void cp_commit() {
    asm volatile("cp.async.commit_group;\n" ::: "memory");
}

// ---------------- tile loader (gmem packed -> smem, zero-filled) ----------------
__device__ __forceinline__ void load_stage(unsigned* su, int stage,
    const unsigned* __restrict__ A, const unsigned* __restrict__ B,
    int m0, int n0, int k0, int M, int N, int K, int lda, int ldb, int tid)
{
    const int q = tid & 7, r0 = tid >> 3;
#pragma unroll
    for (int it = 0; it < 4; it++) {
        int row = r0 + it * 32;
        int gm = m0 + row;
        unsigned* sdst = su + stage * A_STAGE + row * SAP + q * 4;
        int k = k0 + q * 4;
        if (gm < M && k + 3 < K) {
            cp16(sdst, A + (size_t)gm * lda + k);
        } else {
            uint4 v = make_uint4(0, 0, 0, 0);
            if (gm < M) {
                const unsigned* src = A + (size_t)gm * lda;
                if (k + 0 < K) v.x = src[k + 0];
                if (k + 1 < K) v.y = src[k + 1];
                if (k + 2 < K) v.z = src[k + 2];
                if (k + 3 < K) v.w = src[k + 3];
            }
            *(uint4*)sdst = v;
        }
    }
#pragma unroll
    for (int it = 0; it < 2; it++) {
        int row = r0 + it * 32;
        int gn = n0 + row;
        unsigned* sdst = su + B_POOL + stage * B_STAGE + row * SBP + q * 4;
        int k = k0 + q * 4;
        if (gn < N && k + 3 < K) {
            cp16(sdst, B + (size_t)gn * ldb + k);
        } else {
            uint4 v = make_uint4(0, 0, 0, 0);
            if (gn < N) {
                const unsigned* src = B + (size_t)gn * ldb;
                if (k + 0 < K) v.x = src[k + 0];
                if (k + 1 < K) v.y = src[k + 1];
                if (k + 2 < K) v.z = src[k + 2];
                if (k + 3 < K) v.w = src[k + 3];
            }
            *(uint4*)sdst = v;
        }
    }
}

// ---------------- per-stage MMA compute (R2/R8/R10-proven) ----------------
__device__ __forceinline__ void compute_stage(const unsigned* su, int stage,
    float (&acc)[2][4][4], int wm, int wn, int g, int q2)
{
    const unsigned* sa = su + stage * A_STAGE;
    const unsigned* sb = su + B_POOL + stage * B_STAGE;
#pragma unroll
    for (int kk = 0; kk < BK; kk += 16) {
        unsigned ah[2][4], al[2][4], bh[4][2], bl[4][2];
#pragma unroll
        for (int i = 0; i < 2; i++) {
            int r = wm + i * 16 + g;
            uint2 w0 = *(const uint2*)(sa + r * SAP + kk + q2);
            uint2 w1 = *(const uint2*)(sa + (r + 8) * SAP + kk + q2);
            uint2 w2 = *(const uint2*)(sa + r * SAP + kk + 8 + q2);
            uint2 w3 = *(const uint2*)(sa + (r + 8) * SAP + kk + 8 + q2);
            ah[i][0] = __byte_perm(w0.x, w0.y, 0x5410); al[i][0] = __byte_perm(w0.x, w0.y, 0x7632);
            ah[i][1] = __byte_perm(w1.x, w1.y, 0x5410); al[i][1] = __byte_perm(w1.x, w1.y, 0x7632);
            ah[i][2] = __byte_perm(w2.x, w2.y, 0x5410); al[i][2] = __byte_perm(w2.x, w2.y, 0x7632);
            ah[i][3] = __byte_perm(w3.x, w3.y, 0x5410); al[i][3] = __byte_perm(w3.x, w3.y, 0x7632);
        }
#pragma unroll
        for (int j = 0; j < 4; j++) {
            int c = wn + j * 8 + g;
            uint2 u0 = *(const uint2*)(sb + c * SBP + kk + q2);
            uint2 u1 = *(const uint2*)(sb + c * SBP + kk + 8 + q2);
            bh[j][0] = __byte_perm(u0.x, u0.y, 0x5410); bl[j][0] = __byte_perm(u0.x, u0.y, 0x7632);
            bh[j][1] = __byte_perm(u1.x, u1.y, 0x5410); bl[j][1] = __byte_perm(u1.x, u1.y, 0x7632);
        }
#pragma unroll
        for (int i = 0; i < 2; i++)
#pragma unroll
            for (int j = 0; j < 4; j++) {
                MMA_OP(acc[i][j], ah[i], bh[j]);
                MMA_OP(acc[i][j], ah[i], bl[j]);
                MMA_OP(acc[i][j], al[i], bh[j]);
            }
    }
}

// ---------------- GEMM: C = alpha * A[M][K] * B[N][K]^T ----------------
template <int MODE>
__global__ __launch_bounds__(256, 2)
void gemm_p(float* Cg)
{
    extern __shared__ unsigned su[];

    const unsigned *A, *B;
    int M, N, K, lda, ldb;
    float alpha = 1.0f;
    unsigned* outU = nullptr;
    float* outF = nullptr;
    int rs = 0, m0, n0, spart = 0;

    if (MODE == MODE_VKQ) {
        int bx = blockIdx.x;
        if (bx < 1500) {            // V: x(15) y(25) z(4 heads)
            int x = bx % 15; int t = bx / 15; int y = t % 25; int z = t / 25;
            A = g_embap; B = g_Wvp + (size_t)z * 921600;
            M = 3136; N = 960; K = 960; lda = 960; ldb = 960;
            outU = g_Vp + (size_t)z * 960; rs = 3840;
            m0 = y * BM; n0 = x * BN;
        } else if (bx < 3548) {     // K: x(4) y(8) z(64 = h*16+b)
            int l = bx - 1500; int x = l & 3; int y = (l >> 2) & 7; int z = l >> 5;
            A = g_Wkp + (size_t)(z >> 4) * 921600;
            B = g_embap + (size_t)(z & 15) * 188160;
            M = 960; N = 196; K = 960; lda = 960; ldb = 960;
            outU = g_Ktp + (size_t)z * 188160; rs = 196;
            m0 = y * BM; n0 = x * BN;
        } else {                    // Q: z(64 = b*4+h), rem(32) -> scale/x/y
            int l = bx - 3548; int z = l >> 5; int rem = l & 31;
            int s = (rem < 4) ? 0 : (rem < 8) ? 1 : (rem < 16) ? 2 : 3;
            const int pref[4] = {0, 4, 8, 16};
            int loc = rem - pref[s];
            int x = loc & 3, y = loc >> 2;
            int ch = 64 << s;
            A = g_Wqp + QWOFF(s) + (size_t)(z & 3) * ch * ch;
            B = g_embp + COFF(s) + (size_t)(z >> 2) * 196 * ch;
            M = ch; N = 196; K = ch; lda = ch; ldb = ch;
            outU = g_Qp + QPOFF(s) + (size_t)z * ch * 196; rs = 196;
            m0 = y * BM; n0 = x * BN;
        }
    } else if (MODE == MODE_S) {
        int z = blockIdx.z;
        int bx = blockIdx.x;
        int s = (bx < 15) ? 0 : (bx < 30) ? 1 : (bx < 60) ? 2 : 3;
        const int pref[4] = {0, 15, 30, 60};
        int loc = bx - pref[s];
        int x = loc % 15, y = loc / 15;
        int ch = 64 << s;
        A = g_Qp + QPOFF(s) + (size_t)z * ch * 196;
        B = g_Ktp + (size_t)((z & 3) * 16 + (z >> 2)) * 188160;
        M = ch; N = 960; K = 196; lda = 196; ldb = 196;
        alpha = 0.032274861218395144f;            // 1/sqrt(960)
        outF = g_S + SOFF(s) + (size_t)(z >> 2) * ch * 3840 + (z & 3) * 960; rs = 3840;
        const int PB[4] = {0, 960, 1920, 3840};
        const int T[4] = {15, 15, 30, 60};
        spart = PB[s] + z * T[s] + y * 15 + x;
        m0 = y * BM; n0 = x * BN;
    } else if (MODE == MODE_CTX) {               // split by head: z = b*4+h
        int z = blockIdx.z;
        int b = z >> 2, h = z & 3;
        int bx = blockIdx.x;
        int s = (bx < 2) ? 0 : (bx < 6) ? 1 : (bx < 14) ? 2 : 3;
        const int pref[4] = {0, 2, 6, 14};
        int loc = bx - pref[s];
        int x = loc & ((1 << s) - 1), y = loc >> s;
        int ch = 64 << s;
        A = g_Vp + (size_t)b * 752640 + h * 960;
        B = g_Pp + SOFF(s) + (size_t)b * ch * 3840 + h * 960;
        M = 196; N = ch; K = 960; lda = 3840; ldb = 3840;
        alpha = 0.25f;                            // head mean
        outF = g_ctxh + (size_t)h * 3010560 + COFF(s) + (size_t)b * 196 * ch; rs = ch;
        m0 = y * BM; n0 = x * BN;
    } else {                                      // OUT: z = b
        int z = blockIdx.z;
        int bx = blockIdx.x;
        int s = (bx < 2) ? 0 : (bx < 6) ? 1 : (bx < 14) ? 2 : 3;
        const int pref[4] = {0, 2, 6, 14};
        int loc = bx - pref[s];
        int x = loc & ((1 << s) - 1), y = loc >> s;
        int ch = 64 << s;
        A = g_ctxp + COFF(s) + (size_t)z * 196 * ch;
        B = g_Wop + WOFF(s);
        M = 196; N = ch; K = ch; lda = ch; ldb = ch;
        outF = Cg + COFF(s) + (size_t)z * 196 * ch; rs = ch;
        m0 = y * BM; n0 = x * BN;
    }

    const int tid = threadIdx.x;
    const int warp = tid >> 5, lane = tid & 31;
    const int wm = (warp >> 1) * 32, wn = (warp & 1) * 32;
    const int g = lane >> 2, q2 = (lane & 3) * 2;

    float acc[2][4][4];
#pragma unroll
    for (int i = 0; i < 2; i++)
#pragma unroll
        for (int j = 0; j < 4; j++)
#pragma unroll
            for (int r = 0; r < 4; r++) acc[i][j][r] = 0.0f;

    const int nch = (K + BK - 1) / BK;
    const int pre = (STAGES - 1 < nch) ? STAGES - 1 : nch;
    for (int st = 0; st < pre; st++) {
        load_stage(su, st, A, B, m0, n0, st * BK, M, N, K, lda, ldb, tid);
        cp_commit();
    }
    for (int c = 0; c < nch; c++) {
        if (c + STAGES - 1 < nch) {
            load_stage(su, (c + STAGES - 1) % STAGES, A, B, m0, n0,
                       (c + STAGES - 1) * BK, M, N, K, lda, ldb, tid);
            cp_commit();
        }
        int issued = (c + STAGES < nch) ? c + STAGES : nch;
        int pend = issued - 1 - c;
        if (pend >= 1) asm volatile("cp.async.wait_group 1;\n" ::: "memory");
        else           asm volatile("cp.async.wait_group 0;\n" ::: "memory");
        __syncthreads();
        compute_stage(su, c % STAGES, acc, wm, wn, g, q2);
        __syncthreads();
    }

    // ---- epilogue ----
    float sp = 0.f, ssp = 0.f;
#pragma unroll
    for (int i = 0; i < 2; i++) {
#pragma unroll
        for (int rr = 0; rr < 2; rr++) {
            int m = m0 + wm + i * 16 + g + rr * 8;
            if (m >= M) continue;
#pragma unroll
            for (int j = 0; j < 4; j++) {
                int n = n0 + wn + j * 8 + q2;
                if (n >= N) continue;
                float v0 = acc[i][j][rr * 2]     * alpha;
                float v1 = acc[i][j][rr * 2 + 1] * alpha;
                if (MODE == MODE_VKQ) {
                    *(uint2*)(outU + (size_t)m * rs + n) = pack2x(v0, v1);
                } else {
                    *(float2*)(outF + (size_t)m * rs + n) = make_float2(v0, v1);
                    if (MODE == MODE_S) {
                        sp  += v0 + v1;
                        ssp += v0 * v0 + v1 * v1;
                    }
                }
            }
        }
    }

    if (MODE == MODE_S) {
#pragma unroll
        for (int o = 16; o; o >>= 1) {
            sp  += __shfl_xor_sync(0xFFFFFFFFu, sp,  o);
            ssp += __shfl_xor_sync(0xFFFFFFFFu, ssp, o);
        }
        float* rb = (float*)su;                   // smem free after last compute+sync
        if (lane == 0) { rb[warp * 2] = sp; rb[warp * 2 + 1] = ssp; }
        __syncthreads();
        if (tid == 0) {
            float a = 0.f, b2 = 0.f;
            for (int w = 0; w < 8; w++) { a += rb[2 * w]; b2 += rb[2 * w + 1]; }
            g_part[spart * 2] = a; g_part[spart * 2 + 1] = b2;
        }
    }
}

// ---------------- fused fp32 -> packed split-bf16 (all 15 tensors, x4 vec) -------
struct PackArgs { const float* p[15]; };

__global__ void pack_all(PackArgs pa)
{
    const int nblk[15] = {2940,3600,3600,196,392,784,1568,16,64,256,1024,4,16,64,256};
    int rem = blockIdx.x, seg = 0;
    while (rem >= nblk[seg]) { rem -= nblk[seg]; seg++; }
    int i = rem * 1024 + threadIdx.x * 4;
    float4 v = *(const float4*)(pa.p[seg] + i);
    uint2 a = pack2x(v.x, v.y);
    uint2 b = pack2x(v.z, v.w);
    uint4 o = make_uint4(a.x, a.y, b.x, b.y);
    unsigned* dst;
    switch (seg) {
        case 0:  dst = g_embap; break;
        case 1:  dst = g_Wkp; break;
        case 2:  dst = g_Wvp; break;
        case 3:  dst = g_embp; break;
        case 4:  dst = g_embp + 200704; break;
        case 5:  dst = g_embp + 602112; break;
        case 6:  dst = g_embp + 1404928; break;
        case 7:  dst = g_Wqp; break;
        case 8:  dst = g_Wqp + 16384; break;
        case 9:  dst = g_Wqp + 81920; break;
        case 10: dst = g_Wqp + 344064; break;
        case 11: dst = g_Wop; break;
        case 12: dst = g_Wop + 4096; break;
        case 13: dst = g_Wop + 20480; break;
        default: dst = g_Wop + 86016; break;
    }
    *(uint4*)(dst + i) = o;
}

// ---------------- combine per-tile partials -> per-(s,z) mean & inv ----------------
__global__ void stats_combine()
{
    const int sz = blockIdx.x;            // 0..255 : s = sz>>6, zz = sz&63
    const int s = sz >> 6, zz = sz & 63;
    const int Ts[4]  = {15, 15, 30, 60};
    const int PBs[4] = {0, 960, 1920, 3840};
    const int base = (PBs[s] + zz * Ts[s]) * 2;
    const int T = Ts[s];
    float sum = 0.f, ss = 0.f;
    for (int i = threadIdx.x; i < T; i += 32) {
        sum += g_part[base + 2 * i];
        ss  += g_part[base + 2 * i + 1];
    }
#pragma unroll
    for (int o = 16; o; o >>= 1) {
        sum += __shfl_xor_sync(0xFFFFFFFFu, sum, o);
        ss  += __shfl_xor_sync(0xFFFFFFFFu, ss,  o);
    }
    if (threadIdx.x == 0) {
        float cnt = (float)((64 << s) * 960);
        float mean = sum / cnt;
        float var = ss / cnt - mean * mean;
        g_stats[sz * 2]     = mean;
        g_stats[sz * 2 + 1] = rsqrtf(var + 1e-5f);
    }
}

// ---------------- instance-norm + softmax (all scales) -> packed probs ----------
__global__ __launch_bounds__(128)
void softmax_all()
{
    int r = blockIdx.x;                   // prefix {0,4096,12288,28672}
    int s = (r < 4096) ? 0 : (r < 12288) ? 1 : (r < 28672) ? 2 : 3;
    const int pref[4] = {0, 4096, 12288, 28672};
    int loc = r - pref[s];
    const int ch = 64 << s;
    const int h = loc & 3;
    const int t2 = loc >> 2;
    const int d = t2 % ch;
    const int b = t2 / ch;

    const size_t off = (size_t)SOFF(s) + (size_t)b * ch * 3840 + (size_t)d * 3840 + (size_t)h * 960;
    const float* p = g_S + off;
    unsigned* po = g_Pp + off;

    const int zz = b * 4 + h;
    const float mean = g_stats[(s * 64 + zz) * 2];
    const float inv  = g_stats[(s * 64 + zz) * 2 + 1];

    const int t = threadIdx.x;
    const int warp = t >> 5, lane = t & 31;
    const bool act = t < 120;             // 120 threads x 8 elems = 960
    __shared__ float sh[4];

    float v[8];
    float mx = -1e30f;
    if (act) {
        float4 a = *(const float4*)(p + t * 8);
        float4 c = *(const float4*)(p + t * 8 + 4);
        v[0] = (a.x - mean) * inv; v[1] = (a.y - mean) * inv;
        v[2] = (a.z - mean) * inv; v[3] = (a.w - mean) * inv;
        v[4] = (c.x - mean) * inv; v[5] = (c.y - mean) * inv;
        v[6] = (c.z - mean) * inv; v[7] = (c.w - mean) * inv;
#pragma unroll
        for (int k = 0; k < 8; k++) mx = fmaxf(mx, v[k]);
    }
#pragma unroll
    for (int o = 16; o; o >>= 1) mx = fmaxf(mx, __shfl_xor_sync(0xFFFFFFFFu, mx, o));
    if (lane == 0) sh[warp] = mx;
    __syncthreads();
    mx = fmaxf(fmaxf(sh[0], sh[1]), fmaxf(sh[2], sh[3]));
    __syncthreads();

    float lsum = 0.f;
    if (act) {
#pragma unroll
        for (int k = 0; k < 8; k++) { v[k] = __expf(v[k] - mx); lsum += v[k]; }
    }
#pragma unroll
    for (int o = 16; o; o >>= 1) lsum += __shfl_xor_sync(0xFFFFFFFFu, lsum, o);
    if (lane == 0) sh[warp] = lsum;
    __syncthreads();
    const float rden = 1.0f / (((sh[0] + sh[1]) + sh[2]) + sh[3]);

    if (act) {
        uint2 p0 = pack2x(v[0] * rden, v[1] * rden);
        uint2 p1 = pack2x(v[2] * rden, v[3] * rden);
        uint2 p2 = pack2x(v[4] * rden, v[5] * rden);
        uint2 p3 = pack2x(v[6] * rden, v[7] * rden);
        *(uint4*)(po + t * 8)     = make_uint4(p0.x, p0.y, p1.x, p1.y);
        *(uint4*)(po + t * 8 + 4) = make_uint4(p2.x, p2.y, p3.x, p3.y);
    }
}

// ---------------- sum 4 head-partials -> packed ctx (fixed order) ----------------
__global__ void ctx_combine()
{
    int i = (blockIdx.x * 256 + threadIdx.x) * 4;
    if (i >= 3010560) return;
    float4 a = *(const float4*)(g_ctxh + i);
    float4 b = *(const float4*)(g_ctxh + 3010560 + i);
    float4 c = *(const float4*)(g_ctxh + 6021120 + i);
    float4 d = *(const float4*)(g_ctxh + 9031680 + i);
    uint2 o01 = pack2x(((a.x + b.x) + c.x) + d.x, ((a.y + b.y) + c.y) + d.y);
    uint2 o23 = pack2x(((a.z + b.z) + c.z) + d.z, ((a.w + b.w) + c.w) + d.w);
    *(uint4*)(g_ctxp + i) = make_uint4(o01.x, o01.y, o23.x, o23.y);
}

// ---------------- launch ----------------
extern "C" void kernel_launch(void* const* d_in, const int* in_sizes, int n_in,
                              void* d_out, int out_size)
{
    float* out = (float*)d_out;

    cudaFuncSetAttribute((const void*)gemm_p<MODE_VKQ>, cudaFuncAttributeMaxDynamicSharedMemorySize, SMEM_BYTES);
    cudaFuncSetAttribute((const void*)gemm_p<MODE_S>,   cudaFuncAttributeMaxDynamicSharedMemorySize, SMEM_BYTES);
    cudaFuncSetAttribute((const void*)gemm_p<MODE_CTX>, cudaFuncAttributeMaxDynamicSharedMemorySize, SMEM_BYTES);
    cudaFuncSetAttribute((const void*)gemm_p<MODE_OUT>, cudaFuncAttributeMaxDynamicSharedMemorySize, SMEM_BYTES);

    // fused input packing: emb_all, Wk, Wv, emb0-3, Wq0-3, Wo0-3
    PackArgs pa;
    pa.p[0] = (const float*)d_in[4];   // emb_all
    pa.p[1] = (const float*)d_in[13];  // Wk
    pa.p[2] = (const float*)d_in[14];  // Wv
    pa.p[3] = (const float*)d_in[0];   // emb0
    pa.p[4] = (const float*)d_in[1];
    pa.p[5] = (const float*)d_in[2];
    pa.p[6] = (const float*)d_in[3];
    pa.p[7] = (const float*)d_in[5];   // Wq0
    pa.p[8] = (const float*)d_in[7];
    pa.p[9] = (const float*)d_in[9];
    pa.p[10] = (const float*)d_in[11];
    pa.p[11] = (const float*)d_in[6];  // Wo0
    pa.p[12] = (const float*)d_in[8];
    pa.p[13] = (const float*)d_in[10];
    pa.p[14] = (const float*)d_in[12];
    pack_all<<<14780, 256>>>(pa);

    // V (1500 long blocks first) + K (2048) + Q (2048) merged
    gemm_p<MODE_VKQ><<<5596, 256, SMEM_BYTES>>>(nullptr);

    // scores (with fused instance-norm partial stats)
    gemm_p<MODE_S><<<dim3(120, 1, 64), 256, SMEM_BYTES>>>(nullptr);

    stats_combine<<<256, 32>>>();
    softmax_all<<<61440, 128>>>();

    // ctx, split per head (z = b*4+h), fp32 partials
    gemm_p<MODE_CTX><<<dim3(30, 1, 64), 256, SMEM_BYTES>>>(nullptr);
    ctx_combine<<<2940, 256>>>();

    // out projection
    gemm_p<MODE_OUT><<<dim3(30, 1, 16), 256, SMEM_BYTES>>>(out);
}

// round 13
// speedup vs baseline: 3.6012x; 1.0012x over previous
#include <cuda_runtime.h>
#include <cuda_bf16.h>
#include <cstdint>
#include <math.h>

// B=16, N=196, KV=960, H=4, chs={64,128,256,512}

#define BM 128
#define BN 64
#define BK 32
#define STAGES 2
#define SAP 40                    // A smem row stride (u32), padded
#define SBP 40
#define A_STAGE (BM*SAP)          // 5120 u32
#define B_STAGE (BN*SBP)          // 2560 u32
#define B_POOL  (STAGES*A_STAGE)
#define SMEM_BYTES ((STAGES*(A_STAGE+B_STAGE))*4)   // 61440

#define MODE_VKQ 0
#define MODE_S   1
#define MODE_CTX 2
#define MODE_OUT 3

// ---------------- packed split-bf16 scratch (u32 = lo<<16 | hi) ----------------
__device__ unsigned g_embap[3136*960];              // emb_all packed [3136][960]
__device__ unsigned g_Wkp  [4*960*960];             // [h][j][k]
__device__ unsigned g_Wvp  [4*960*960];
__device__ unsigned g_embp [3136*960];              // 4 embs concatenated
__device__ unsigned g_Wqp  [1392640];               // 4 scales of [h][d][c]
__device__ unsigned g_Wop  [348160];                // 4 scales of [e][d]
__device__ unsigned g_Ktp  [(size_t)4*16*960*196];  // [h*16+b][j][n]
__device__ unsigned g_Vp   [(size_t)16*196*3840];   // [b][n][h*960+j]
__device__ unsigned g_Qp   [12042240];              // ALL scales [s][b*4+h][d][n]
__device__ float    g_S    [58982400];              // ALL scales fp32 scores
__device__ unsigned g_Pp   [58982400];              // probs packed, same layout
__device__ float    g_ctxh [12042240];              // 4 head-partials x all-scale ctx (fp32)
__device__ unsigned g_ctxp [3010560];               // ALL scales [s][b][n][d] packed
__device__ float    g_part [15360];                 // 7680 tiles x (sum,sumsq)
__device__ float    g_stats[512];                   // per (s,z): mean, inv

// per-scale offset tables (compile-time)
#define SOFF(s)  ((s)==0?0:((s)==1?3932160:((s)==2?11796480:27525120)))
#define QPOFF(s) ((s)==0?0:((s)==1?802816:((s)==2?2408448:5619712)))
#define COFF(s)  ((s)==0?0:((s)==1?200704:((s)==2?602112:1404928)))
#define QWOFF(s) ((s)==0?0:((s)==1?16384:((s)==2?81920:344064)))
#define WOFF(s)  ((s)==0?0:((s)==1?4096:((s)==2?20480:86016)))

// ---------------- helpers ----------------
// pair pack: two fp32 -> two packed u32 (lo<<16 | hi), bf16 _rn rounding
__device__ __forceinline__ uint2 pack2x(float v0, float v1) {
    __nv_bfloat162 H = __floats2bfloat162_rn(v0, v1);
    unsigned Hu = *(unsigned*)&H;                     // [h1 | h0]
    float f0 = __uint_as_float(Hu << 16);
    float f1 = __uint_as_float(Hu & 0xffff0000u);
    __nv_bfloat162 L = __floats2bfloat162_rn(v0 - f0, v1 - f1);
    unsigned Lu = *(unsigned*)&L;
    return make_uint2(__byte_perm(Hu, Lu, 0x5410), __byte_perm(Hu, Lu, 0x7632));
}

#define MMA_OP(d, a, b) asm volatile( \
    "mma.sync.aligned.m16n8k16.row.col.f32.bf16.bf16.f32 " \
    "{%0,%1,%2,%3},{%4,%5,%6,%7},{%8,%9},{%0,%1,%2,%3};" \
    : "+f"(d[0]), "+f"(d[1]), "+f"(d[2]), "+f"(d[3]) \
    : "r"(a[0]), "r"(a[1]), "r"(a[2]), "r"(a[3]), "r"(b[0]), "r"(b[1]))

__device__ __forceinline__ void cp16(unsigned* sdst, const unsigned* g) {
    unsigned sa = (unsigned)__cvta_generic_to_shared(sdst);
    asm volatile("cp.async.cg.shared.global [%0],[%1],16;\n" :: "r"(sa), "l"(g) : "memory");
}
__device__ __forceinline__ void cp_commit() {
    asm volatile("cp.async.commit_group;\n" ::: "memory");
}

// ---------------- tile loader (gmem packed -> smem, zero-filled) ----------------
__device__ __forceinline__ void load_stage(unsigned* su, int stage,
    const unsigned* __restrict__ A, const unsigned* __restrict__ B,
    int m0, int n0, int k0, int M, int N, int K, int lda, int ldb, int tid)
{
    const int q = tid & 7, r0 = tid >> 3;
#pragma unroll
    for (int it = 0; it < 4; it++) {
        int row = r0 + it * 32;
        int gm = m0 + row;
        unsigned* sdst = su + stage * A_STAGE + row * SAP + q * 4;
        int k = k0 + q * 4;
        if (gm < M && k + 3 < K) {
            cp16(sdst, A + (size_t)gm * lda + k);
        } else {
            uint4 v = make_uint4(0, 0, 0, 0);
            if (gm < M) {
                const unsigned* src = A + (size_t)gm * lda;
                if (k + 0 < K) v.x = src[k + 0];
                if (k + 1 < K) v.y = src[k + 1];
                if (k + 2 < K) v.z = src[k + 2];
                if (k + 3 < K) v.w = src[k + 3];
            }
            *(uint4*)sdst = v;
        }
    }
#pragma unroll
    for (int it = 0; it < 2; it++) {
        int row = r0 + it * 32;
        int gn = n0 + row;
        unsigned* sdst = su + B_POOL + stage * B_STAGE + row * SBP + q * 4;
        int k = k0 + q * 4;
        if (gn < N && k + 3 < K) {
            cp16(sdst, B + (size_t)gn * ldb + k);
        } else {
            uint4 v = make_uint4(0, 0, 0, 0);
            if (gn < N) {
                const unsigned* src = B + (size_t)gn * ldb;
                if (k + 0 < K) v.x = src[k + 0];
                if (k + 1 < K) v.y = src[k + 1];
                if (k + 2 < K) v.z = src[k + 2];
                if (k + 3 < K) v.w = src[k + 3];
            }
            *(uint4*)sdst = v;
        }
    }
}

// ---------------- per-stage MMA compute: 3 passes over 8 independent accs ----------
// Per-accumulator term order unchanged (hh, hl, lh) => bit-identical results;
// reuse distance per acc goes 1 -> 8 instructions, hiding HMMA latency.
__device__ __forceinline__ void compute_stage(const unsigned* su, int stage,
    float (&acc)[2][4][4], int wm, int wn, int g, int q2)
{
    const unsigned* sa = su + stage * A_STAGE;
    const unsigned* sb = su + B_POOL + stage * B_STAGE;
#pragma unroll
    for (int kk = 0; kk < BK; kk += 16) {
        unsigned ah[2][4], al[2][4], bh[4][2], bl[4][2];
#pragma unroll
        for (int i = 0; i < 2; i++) {
            int r = wm + i * 16 + g;
            uint2 w0 = *(const uint2*)(sa + r * SAP + kk + q2);
            uint2 w1 = *(const uint2*)(sa + (r + 8) * SAP + kk + q2);
            uint2 w2 = *(const uint2*)(sa + r * SAP + kk + 8 + q2);
            uint2 w3 = *(const uint2*)(sa + (r + 8) * SAP + kk + 8 + q2);
            ah[i][0] = __byte_perm(w0.x, w0.y, 0x5410); al[i][0] = __byte_perm(w0.x, w0.y, 0x7632);
            ah[i][1] = __byte_perm(w1.x, w1.y, 0x5410); al[i][1] = __byte_perm(w1.x, w1.y, 0x7632);
            ah[i][2] = __byte_perm(w2.x, w2.y, 0x5410); al[i][2] = __byte_perm(w2.x, w2.y, 0x7632);
            ah[i][3] = __byte_perm(w3.x, w3.y, 0x5410); al[i][3] = __byte_perm(w3.x, w3.y, 0x7632);
        }
#pragma unroll
        for (int j = 0; j < 4; j++) {
            int c = wn + j * 8 + g;
            uint2 u0 = *(const uint2*)(sb + c * SBP + kk + q2);
            uint2 u1 = *(const uint2*)(sb + c * SBP + kk + 8 + q2);
            bh[j][0] = __byte_perm(u0.x, u0.y, 0x5410); bl[j][0] = __byte_perm(u0.x, u0.y, 0x7632);
            bh[j][1] = __byte_perm(u1.x, u1.y, 0x5410); bl[j][1] = __byte_perm(u1.x, u1.y, 0x7632);
        }
        // pass 1: hi*hi
#pragma unroll
        for (int i = 0; i < 2; i++)
#pragma unroll
            for (int j = 0; j < 4; j++)
                MMA_OP(acc[i][j], ah[i], bh[j]);
        // pass 2: hi*lo
#pragma unroll
        for (int i = 0; i < 2; i++)
#pragma unroll
            for (int j = 0; j < 4; j++)
                MMA_OP(acc[i][j], ah[i], bl[j]);
        // pass 3: lo*hi
#pragma unroll
        for (int i = 0; i < 2; i++)
#pragma unroll
            for (int j = 0; j < 4; j++)
                MMA_OP(acc[i][j], al[i], bh[j]);
    }
}

// ---------------- GEMM: C = alpha * A[M][K] * B[N][K]^T ----------------
template <int MODE>
__global__ __launch_bounds__(256, 2)
void gemm_p(float* Cg)
{
    extern __shared__ unsigned su[];

    const unsigned *A, *B;
    int M, N, K, lda, ldb;
    float alpha = 1.0f;
    unsigned* outU = nullptr;
    float* outF = nullptr;
    int rs = 0, m0, n0, spart = 0;

    if (MODE == MODE_VKQ) {
        int bx = blockIdx.x;
        if (bx < 1500) {            // V: x(15) y(25) z(4 heads)
            int x = bx % 15; int t = bx / 15; int y = t % 25; int z = t / 25;
            A = g_embap; B = g_Wvp + (size_t)z * 921600;
            M = 3136; N = 960; K = 960; lda = 960; ldb = 960;
            outU = g_Vp + (size_t)z * 960; rs = 3840;
            m0 = y * BM; n0 = x * BN;
        } else if (bx < 3548) {     // K: x(4) y(8) z(64 = h*16+b)
            int l = bx - 1500; int x = l & 3; int y = (l >> 2) & 7; int z = l >> 5;
            A = g_Wkp + (size_t)(z >> 4) * 921600;
            B = g_embap + (size_t)(z & 15) * 188160;
            M = 960; N = 196; K = 960; lda = 960; ldb = 960;
            outU = g_Ktp + (size_t)z * 188160; rs = 196;
            m0 = y * BM; n0 = x * BN;
        } else {                    // Q: z(64 = b*4+h), rem(32) -> scale/x/y
            int l = bx - 3548; int z = l >> 5; int rem = l & 31;
            int s = (rem < 4) ? 0 : (rem < 8) ? 1 : (rem < 16) ? 2 : 3;
            const int pref[4] = {0, 4, 8, 16};
            int loc = rem - pref[s];
            int x = loc & 3, y = loc >> 2;
            int ch = 64 << s;
            A = g_Wqp + QWOFF(s) + (size_t)(z & 3) * ch * ch;
            B = g_embp + COFF(s) + (size_t)(z >> 2) * 196 * ch;
            M = ch; N = 196; K = ch; lda = ch; ldb = ch;
            outU = g_Qp + QPOFF(s) + (size_t)z * ch * 196; rs = 196;
            m0 = y * BM; n0 = x * BN;
        }
    } else if (MODE == MODE_S) {
        int z = blockIdx.z;
        int bx = blockIdx.x;
        int s = (bx < 15) ? 0 : (bx < 30) ? 1 : (bx < 60) ? 2 : 3;
        const int pref[4] = {0, 15, 30, 60};
        int loc = bx - pref[s];
        int x = loc % 15, y = loc / 15;
        int ch = 64 << s;
        A = g_Qp + QPOFF(s) + (size_t)z * ch * 196;
        B = g_Ktp + (size_t)((z & 3) * 16 + (z >> 2)) * 188160;
        M = ch; N = 960; K = 196; lda = 196; ldb = 196;
        alpha = 0.032274861218395144f;            // 1/sqrt(960)
        outF = g_S + SOFF(s) + (size_t)(z >> 2) * ch * 3840 + (z & 3) * 960; rs = 3840;
        const int PB[4] = {0, 960, 1920, 3840};
        const int T[4] = {15, 15, 30, 60};
        spart = PB[s] + z * T[s] + y * 15 + x;
        m0 = y * BM; n0 = x * BN;
    } else if (MODE == MODE_CTX) {               // split by head: z = b*4+h
        int z = blockIdx.z;
        int b = z >> 2, h = z & 3;
        int bx = blockIdx.x;
        int s = (bx < 2) ? 0 : (bx < 6) ? 1 : (bx < 14) ? 2 : 3;
        const int pref[4] = {0, 2, 6, 14};
        int loc = bx - pref[s];
        int x = loc & ((1 << s) - 1), y = loc >> s;
        int ch = 64 << s;
        A = g_Vp + (size_t)b * 752640 + h * 960;
        B = g_Pp + SOFF(s) + (size_t)b * ch * 3840 + h * 960;
        M = 196; N = ch; K = 960; lda = 3840; ldb = 3840;
        alpha = 0.25f;                            // head mean
        outF = g_ctxh + (size_t)h * 3010560 + COFF(s) + (size_t)b * 196 * ch; rs = ch;
        m0 = y * BM; n0 = x * BN;
    } else {                                      // OUT: z = b
        int z = blockIdx.z;
        int bx = blockIdx.x;
        int s = (bx < 2) ? 0 : (bx < 6) ? 1 : (bx < 14) ? 2 : 3;
        const int pref[4] = {0, 2, 6, 14};
        int loc = bx - pref[s];
        int x = loc & ((1 << s) - 1), y = loc >> s;
        int ch = 64 << s;
        A = g_ctxp + COFF(s) + (size_t)z * 196 * ch;
        B = g_Wop + WOFF(s);
        M = 196; N = ch; K = ch; lda = ch; ldb = ch;
        outF = Cg + COFF(s) + (size_t)z * 196 * ch; rs = ch;
        m0 = y * BM; n0 = x * BN;
    }

    const int tid = threadIdx.x;
    const int warp = tid >> 5, lane = tid & 31;
    const int wm = (warp >> 1) * 32, wn = (warp & 1) * 32;
    const int g = lane >> 2, q2 = (lane & 3) * 2;

    float acc[2][4][4];
#pragma unroll
    for (int i = 0; i < 2; i++)
#pragma unroll
        for (int j = 0; j < 4; j++)
#pragma unroll
            for (int r = 0; r < 4; r++) acc[i][j][r] = 0.0f;

    const int nch = (K + BK - 1) / BK;
    const int pre = (STAGES - 1 < nch) ? STAGES - 1 : nch;
    for (int st = 0; st < pre; st++) {
        load_stage(su, st, A, B, m0, n0, st * BK, M, N, K, lda, ldb, tid);
        cp_commit();
    }
    for (int c = 0; c < nch; c++) {
        if (c + STAGES - 1 < nch) {
            load_stage(su, (c + STAGES - 1) % STAGES, A, B, m0, n0,
                       (c + STAGES - 1) * BK, M, N, K, lda, ldb, tid);
            cp_commit();
        }
        int issued = (c + STAGES < nch) ? c + STAGES : nch;
        int pend = issued - 1 - c;
        if (pend >= 1) asm volatile("cp.async.wait_group 1;\n" ::: "memory");
        else           asm volatile("cp.async.wait_group 0;\n" ::: "memory");
        __syncthreads();
        compute_stage(su, c % STAGES, acc, wm, wn, g, q2);
        __syncthreads();
    }

    // ---- epilogue ----
    float sp = 0.f, ssp = 0.f;
#pragma unroll
    for (int i = 0; i < 2; i++) {
#pragma unroll
        for (int rr = 0; rr < 2; rr++) {
            int m = m0 + wm + i * 16 + g + rr * 8;
            if (m >= M) continue;
#pragma unroll
            for (int j = 0; j < 4; j++) {
                int n = n0 + wn + j * 8 + q2;
                if (n >= N) continue;
                float v0 = acc[i][j][rr * 2]     * alpha;
                float v1 = acc[i][j][rr * 2 + 1] * alpha;
                if (MODE == MODE_VKQ) {
                    *(uint2*)(outU + (size_t)m * rs + n) = pack2x(v0, v1);
                } else {
                    *(float2*)(outF + (size_t)m * rs + n) = make_float2(v0, v1);
                    if (MODE == MODE_S) {
                        sp  += v0 + v1;
                        ssp += v0 * v0 + v1 * v1;
                    }
                }
            }
        }
    }

    if (MODE == MODE_S) {
#pragma unroll
        for (int o = 16; o; o >>= 1) {
            sp  += __shfl_xor_sync(0xFFFFFFFFu, sp,  o);
            ssp += __shfl_xor_sync(0xFFFFFFFFu, ssp, o);
        }
        float* rb = (float*)su;                   // smem free after last compute+sync
        if (lane == 0) { rb[warp * 2] = sp; rb[warp * 2 + 1] = ssp; }
        __syncthreads();
        if (tid == 0) {
            float a = 0.f, b2 = 0.f;
            for (int w = 0; w < 8; w++) { a += rb[2 * w]; b2 += rb[2 * w + 1]; }
            g_part[spart * 2] = a; g_part[spart * 2 + 1] = b2;
        }
    }
}

// ---------------- fused fp32 -> packed split-bf16 (all 15 tensors, x4 vec) -------
struct PackArgs { const float* p[15]; };

__global__ void pack_all(PackArgs pa)
{
    const int nblk[15] = {2940,3600,3600,196,392,784,1568,16,64,256,1024,4,16,64,256};
    int rem = blockIdx.x, seg = 0;
    while (rem >= nblk[seg]) { rem -= nblk[seg]; seg++; }
    int i = rem * 1024 + threadIdx.x * 4;
    float4 v = *(const float4*)(pa.p[seg] + i);
    uint2 a = pack2x(v.x, v.y);
    uint2 b = pack2x(v.z, v.w);
    uint4 o = make_uint4(a.x, a.y, b.x, b.y);
    unsigned* dst;
    switch (seg) {
        case 0:  dst = g_embap; break;
        case 1:  dst = g_Wkp; break;
        case 2:  dst = g_Wvp; break;
        case 3:  dst = g_embp; break;
        case 4:  dst = g_embp + 200704; break;
        case 5:  dst = g_embp + 602112; break;
        case 6:  dst = g_embp + 1404928; break;
        case 7:  dst = g_Wqp; break;
        case 8:  dst = g_Wqp + 16384; break;
        case 9:  dst = g_Wqp + 81920; break;
        case 10: dst = g_Wqp + 344064; break;
        case 11: dst = g_Wop; break;
        case 12: dst = g_Wop + 4096; break;
        case 13: dst = g_Wop + 20480; break;
        default: dst = g_Wop + 86016; break;
    }
    *(uint4*)(dst + i) = o;
}

// ---------------- combine per-tile partials -> per-(s,z) mean & inv ----------------
__global__ void stats_combine()
{
    const int sz = blockIdx.x;            // 0..255 : s = sz>>6, zz = sz&63
    const int s = sz >> 6, zz = sz & 63;
    const int Ts[4]  = {15, 15, 30, 60};
    const int PBs[4] = {0, 960, 1920, 3840};
    const int base = (PBs[s] + zz * Ts[s]) * 2;
    const int T = Ts[s];
    float sum = 0.f, ss = 0.f;
    for (int i = threadIdx.x; i < T; i += 32) {
        sum += g_part[base + 2 * i];
        ss  += g_part[base + 2 * i + 1];
    }
#pragma unroll
    for (int o = 16; o; o >>= 1) {
        sum += __shfl_xor_sync(0xFFFFFFFFu, sum, o);
        ss  += __shfl_xor_sync(0xFFFFFFFFu, ss,  o);
    }
    if (threadIdx.x == 0) {
        float cnt = (float)((64 << s) * 960);
        float mean = sum / cnt;
        float var = ss / cnt - mean * mean;
        g_stats[sz * 2]     = mean;
        g_stats[sz * 2 + 1] = rsqrtf(var + 1e-5f);
    }
}

// ---------------- instance-norm + softmax (all scales) -> packed probs ----------
__global__ __launch_bounds__(128)
void softmax_all()
{
    int r = blockIdx.x;                   // prefix {0,4096,12288,28672}
    int s = (r < 4096) ? 0 : (r < 12288) ? 1 : (r < 28672) ? 2 : 3;
    const int pref[4] = {0, 4096, 12288, 28672};
    int loc = r - pref[s];
    const int ch = 64 << s;
    const int h = loc & 3;
    const int t2 = loc >> 2;
    const int d = t2 % ch;
    const int b = t2 / ch;

    const size_t off = (size_t)SOFF(s) + (size_t)b * ch * 3840 + (size_t)d * 3840 + (size_t)h * 960;
    const float* p = g_S + off;
    unsigned* po = g_Pp + off;

    const int zz = b * 4 + h;
    const float mean = g_stats[(s * 64 + zz) * 2];
    const float inv  = g_stats[(s * 64 + zz) * 2 + 1];

    const int t = threadIdx.x;
    const int warp = t >> 5, lane = t & 31;
    const bool act = t < 120;             // 120 threads x 8 elems = 960
    __shared__ float sh[4];

    float v[8];
    float mx = -1e30f;
    if (act) {
        float4 a = *(const float4*)(p + t * 8);
        float4 c = *(const float4*)(p + t * 8 + 4);
        v[0] = (a.x - mean) * inv; v[1] = (a.y - mean) * inv;
        v[2] = (a.z - mean) * inv; v[3] = (a.w - mean) * inv;
        v[4] = (c.x - mean) * inv; v[5] = (c.y - mean) * inv;
        v[6] = (c.z - mean) * inv; v[7] = (c.w - mean) * inv;
#pragma unroll
        for (int k = 0; k < 8; k++) mx = fmaxf(mx, v[k]);
    }
#pragma unroll
    for (int o = 16; o; o >>= 1) mx = fmaxf(mx, __shfl_xor_sync(0xFFFFFFFFu, mx, o));
    if (lane == 0) sh[warp] = mx;
    __syncthreads();
    mx = fmaxf(fmaxf(sh[0], sh[1]), fmaxf(sh[2], sh[3]));
    __syncthreads();

    float lsum = 0.f;
    if (act) {
#pragma unroll
        for (int k = 0; k < 8; k++) { v[k] = __expf(v[k] - mx); lsum += v[k]; }
    }
#pragma unroll
    for (int o = 16; o; o >>= 1) lsum += __shfl_xor_sync(0xFFFFFFFFu, lsum, o);
    if (lane == 0) sh[warp] = lsum;
    __syncthreads();
    const float rden = 1.0f / (((sh[0] + sh[1]) + sh[2]) + sh[3]);

    if (act) {
        uint2 p0 = pack2x(v[0] * rden, v[1] * rden);
        uint2 p1 = pack2x(v[2] * rden, v[3] * rden);
        uint2 p2 = pack2x(v[4] * rden, v[5] * rden);
        uint2 p3 = pack2x(v[6] * rden, v[7] * rden);
        *(uint4*)(po + t * 8)     = make_uint4(p0.x, p0.y, p1.x, p1.y);
        *(uint4*)(po + t * 8 + 4) = make_uint4(p2.x, p2.y, p3.x, p3.y);
    }
}

// ---------------- sum 4 head-partials -> packed ctx (fixed order) ----------------
__global__ void ctx_combine()
{
    int i = (blockIdx.x * 256 + threadIdx.x) * 4;
    if (i >= 3010560) return;
    float4 a = *(const float4*)(g_ctxh + i);
    float4 b = *(const float4*)(g_ctxh + 3010560 + i);
    float4 c = *(const float4*)(g_ctxh + 6021120 + i);
    float4 d = *(const float4*)(g_ctxh + 9031680 + i);
    uint2 o01 = pack2x(((a.x + b.x) + c.x) + d.x, ((a.y + b.y) + c.y) + d.y);
    uint2 o23 = pack2x(((a.z + b.z) + c.z) + d.z, ((a.w + b.w) + c.w) + d.w);
    *(uint4*)(g_ctxp + i) = make_uint4(o01.x, o01.y, o23.x, o23.y);
}

// ---------------- launch ----------------
extern "C" void kernel_launch(void* const* d_in, const int* in_sizes, int n_in,
                              void* d_out, int out_size)
{
    float* out = (float*)d_out;

    cudaFuncSetAttribute((const void*)gemm_p<MODE_VKQ>, cudaFuncAttributeMaxDynamicSharedMemorySize, SMEM_BYTES);
    cudaFuncSetAttribute((const void*)gemm_p<MODE_S>,   cudaFuncAttributeMaxDynamicSharedMemorySize, SMEM_BYTES);
    cudaFuncSetAttribute((const void*)gemm_p<MODE_CTX>, cudaFuncAttributeMaxDynamicSharedMemorySize, SMEM_BYTES);
    cudaFuncSetAttribute((const void*)gemm_p<MODE_OUT>, cudaFuncAttributeMaxDynamicSharedMemorySize, SMEM_BYTES);

    // fused input packing: emb_all, Wk, Wv, emb0-3, Wq0-3, Wo0-3
    PackArgs pa;
    pa.p[0] = (const float*)d_in[4];   // emb_all
    pa.p[1] = (const float*)d_in[13];  // Wk
    pa.p[2] = (const float*)d_in[14];  // Wv
    pa.p[3] = (const float*)d_in[0];   // emb0
    pa.p[4] = (const float*)d_in[1];
    pa.p[5] = (const float*)d_in[2];
    pa.p[6] = (const float*)d_in[3];
    pa.p[7] = (const float*)d_in[5];   // Wq0
    pa.p[8] = (const float*)d_in[7];
    pa.p[9] = (const float*)d_in[9];
    pa.p[10] = (const float*)d_in[11];
    pa.p[11] = (const float*)d_in[6];  // Wo0
    pa.p[12] = (const float*)d_in[8];
    pa.p[13] = (const float*)d_in[10];
    pa.p[14] = (const float*)d_in[12];
    pack_all<<<14780, 256>>>(pa);

    // V (1500 long blocks first) + K (2048) + Q (2048) merged
    gemm_p<MODE_VKQ><<<5596, 256, SMEM_BYTES>>>(nullptr);

    // scores (with fused instance-norm partial stats)
    gemm_p<MODE_S><<<dim3(120, 1, 64), 256, SMEM_BYTES>>>(nullptr);

    stats_combine<<<256, 32>>>();
    softmax_all<<<61440, 128>>>();

    // ctx, split per head (z = b*4+h), fp32 partials
    gemm_p<MODE_CTX><<<dim3(30, 1, 64), 256, SMEM_BYTES>>>(nullptr);
    ctx_combine<<<2940, 256>>>();

    // out projection
    gemm_p<MODE_OUT><<<dim3(30, 1, 16), 256, SMEM_BYTES>>>(out);
}